// round 9
// baseline (speedup 1.0000x reference)
#include <cuda_runtime.h>
#include <cuda_bf16.h>

// Problem constants (FIXED by reference): N=20000, E=160000, NODE_DIM=64, EDGE_DIM=16, H=32, STEPS=3
#define NN     20000
#define EE     160000
#define HD     32
#define ND     64
#define ED     16
#define TSL    576          // padded T row stride: 18 slices of 32 (16 edge-dims + bias + pad)

// Scratch (allocation-free rule: __device__ globals)
__device__ int   g_flag;                     // 1 = float inputs are bf16, 0 = fp32
__device__ float g_h [NN * HD];              // node hidden state (fp32 internal)
__device__ float g_m [NN * HD];              // aggregated messages (fully written by msgB)
__device__ float g_T [NN * TSL];             // per-node tensor (46 MB, L2-resident)
__device__ float g_W2[TSL * HD];             // reshaped edge weight (rows >= 544 zero)
// CSR scratch (rebuilt every replay; deterministic sums)
__device__ int   g_cnt_src[NN], g_cnt_dst[NN];
__device__ int   g_off_src[NN], g_off_dst[NN];
__device__ int   g_cur_src[NN], g_cur_dst[NN];
__device__ int   g_perm [EE];                // src-sorted position -> original edge id
__device__ int   g_psrc [EE];                // src-sorted position -> src node
__device__ int   g_outq [EE];                // src-sorted position -> dst-sorted slot
__device__ float g_msg  [EE * HD];           // messages in dst-sorted order (20.5 MB)

namespace {
struct EagerLoad {                            // materialize device globals at process start
    EagerLoad() { void* p = nullptr; (void)cudaGetSymbolAddress(&p, g_h); }
};
EagerLoad eager_load_;
}

// Dtype-agnostic float load (branch is warp-uniform on g_flag).
__device__ __forceinline__ float ldF(const void* p, long i, int bf) {
    return bf ? __bfloat162float(((const __nv_bfloat16*)p)[i])
              : ((const float*)p)[i];
}

// ---------------------------------------------------------------------------
// Detect input dtype from node_feat bit patterns (see R4 notes).
// ---------------------------------------------------------------------------
__global__ void detectKernel(const unsigned int* __restrict__ nf) {
    int lane = threadIdx.x;
    int cnt = 0;
    for (int i = lane; i < 1024; i += 32) {
        unsigned int e = (nf[i] >> 7) & 0xFF;
        cnt += (e >= 110 && e <= 140) ? 1 : 0;
    }
#pragma unroll
    for (int o = 16; o > 0; o >>= 1) cnt += __shfl_down_sync(0xffffffffu, cnt, o);
    if (lane == 0) g_flag = (cnt > 512) ? 1 : 0;
}

// ---------------------------------------------------------------------------
// CSR setup (per replay): histogram -> scan -> slot assignment. NO ef permute.
// ---------------------------------------------------------------------------
__global__ void zeroCntKernel() {
    int i = blockIdx.x * 256 + threadIdx.x;
    if (i < NN) { g_cnt_src[i] = 0; g_cnt_dst[i] = 0; }
}

__global__ void histKernel(const int* __restrict__ src, const int* __restrict__ dst) {
    int e = blockIdx.x * 256 + threadIdx.x;
    if (e >= EE) return;
    int s = src[e]; if ((unsigned)s >= (unsigned)NN) s = 0;
    int d = dst[e]; if ((unsigned)d >= (unsigned)NN) d = 0;
    atomicAdd(&g_cnt_src[s], 1);
    atomicAdd(&g_cnt_dst[d], 1);
}

// Exclusive prefix scan of both count arrays (1 block, 1024 threads).
__global__ void scanKernel() {
    __shared__ int part[1024];
    int t = threadIdx.x;
#pragma unroll
    for (int a = 0; a < 2; a++) {
        const int* cnt = a ? g_cnt_dst : g_cnt_src;
        int*       off = a ? g_off_dst : g_off_src;
        int*       cur = a ? g_cur_dst : g_cur_src;
        int base = t * 20;                           // 1024*20 >= NN
        int s = 0;
        for (int i = 0; i < 20; i++) {
            int idx = base + i;
            s += (idx < NN) ? cnt[idx] : 0;
        }
        part[t] = s;
        __syncthreads();
        for (int d = 1; d < 1024; d <<= 1) {         // Hillis-Steele inclusive
            int v = (t >= d) ? part[t - d] : 0;
            __syncthreads();
            part[t] += v;
            __syncthreads();
        }
        int run = (t > 0) ? part[t - 1] : 0;         // exclusive base for chunk
        for (int i = 0; i < 20; i++) {
            int idx = base + i;
            if (idx < NN) { off[idx] = run; run += cnt[idx]; cur[idx] = 0; }
        }
        __syncthreads();
    }
}

__global__ void scatterIdxKernel(const int* __restrict__ src, const int* __restrict__ dst) {
    int e = blockIdx.x * 256 + threadIdx.x;
    if (e >= EE) return;
    int s = src[e]; if ((unsigned)s >= (unsigned)NN) s = 0;
    int d = dst[e]; if ((unsigned)d >= (unsigned)NN) d = 0;
    int p = g_off_src[s] + atomicAdd(&g_cur_src[s], 1);
    int q = g_off_dst[d] + atomicAdd(&g_cur_dst[d], 1);
    g_perm[p] = e;
    g_psrc[p] = s;
    g_outq[p] = q;
}

// ---------------------------------------------------------------------------
// Build W2: W2[(d*32+h)*32+k] = W_e[(h*32+k)*16+d]; slice 16 = b_e; 17 = pad 0.
// ---------------------------------------------------------------------------
__global__ void buildW2Kernel(const void* __restrict__ We, const void* __restrict__ be) {
    int bf = g_flag;
    int i = blockIdx.x * 256 + threadIdx.x;
    if (i >= TSL * HD) return;
    int j = i >> 5, k = i & 31;
    int d = j >> 5, h = j & 31;
    float v = 0.0f;
    if (d < 16)       v = ldF(We, (h * 32 + k) * 16 + d, bf);
    else if (d == 16) v = ldF(be, h * 32 + k, bf);
    g_W2[i] = v;
}

// ---------------------------------------------------------------------------
// h = node_feat @ W_np^T + b_np. Warp per node.
// ---------------------------------------------------------------------------
__global__ void nodeProjKernel(const void* __restrict__ nf, const void* __restrict__ W,
                               const void* __restrict__ b) {
    __shared__ float Ws[32 * 65];
    int bf = g_flag;
    int tid = threadIdx.x;
    for (int i = tid; i < 32 * 64; i += 256)
        Ws[(i >> 6) * 65 + (i & 63)] = ldF(W, i, bf);
    __syncthreads();

    int n = blockIdx.x * 8 + (tid >> 5);
    int lane = tid & 31;

    float v0 = ldF(nf, n * 64 + lane, bf);
    float v1 = ldF(nf, n * 64 + 32 + lane, bf);
    float acc = ldF(b, lane, bf);
#pragma unroll
    for (int k = 0; k < 32; k++) {
        float a0 = __shfl_sync(0xffffffffu, v0, k);
        float a1 = __shfl_sync(0xffffffffu, v1, k);
        acc = fmaf(a0, Ws[lane * 65 + k], acc);
        acc = fmaf(a1, Ws[lane * 65 + 32 + k], acc);
    }
    g_h[n * 32 + lane] = acc;
}

// ---------------------------------------------------------------------------
// T[n, j] = sum_k W2[j][k] * h[n][k]
// 296 blocks x 68 nodes (one uniform wave), 288 threads, 2 W2 rows + 4-node ILP.
// ---------------------------------------------------------------------------
__global__ void __launch_bounds__(288, 2) compTKernel() {
    __shared__ __align__(16) float hs[68][32];
    int t = threadIdx.x;                              // 0..287
    int n0 = blockIdx.x * 68;

    float w0[32], w1[32];
#pragma unroll
    for (int k = 0; k < 32; k++) {
        w0[k] = g_W2[t * 32 + k];
        w1[k] = g_W2[(t + 288) * 32 + k];
    }

    for (int i = t; i < 68 * 32; i += 288) {
        int n = n0 + (i >> 5);
        hs[i >> 5][i & 31] = (n < NN) ? g_h[n * 32 + (i & 31)] : 0.0f;
    }
    __syncthreads();

    int nend = NN - n0;
    if (nend > 68) nend = 68;
    for (int nl = 0; nl < nend; nl += 4) {            // nend % 4 == 0 always
        const float4* p0 = reinterpret_cast<const float4*>(hs[nl + 0]);
        const float4* p1 = reinterpret_cast<const float4*>(hs[nl + 1]);
        const float4* p2 = reinterpret_cast<const float4*>(hs[nl + 2]);
        const float4* p3 = reinterpret_cast<const float4*>(hs[nl + 3]);
        float a0 = 0.f, a1 = 0.f, a2 = 0.f, a3 = 0.f;  // j = t
        float b0 = 0.f, b1 = 0.f, b2 = 0.f, b3 = 0.f;  // j = t + 288
#pragma unroll
        for (int kk = 0; kk < 8; kk++) {
            float4 h0 = p0[kk], h1 = p1[kk], h2 = p2[kk], h3 = p3[kk];
#pragma unroll
            for (int q = 0; q < 4; q++) {
                float hv0 = (&h0.x)[q], hv1 = (&h1.x)[q];
                float hv2 = (&h2.x)[q], hv3 = (&h3.x)[q];
                float wa = w0[kk * 4 + q], wb = w1[kk * 4 + q];
                a0 = fmaf(hv0, wa, a0); a1 = fmaf(hv1, wa, a1);
                a2 = fmaf(hv2, wa, a2); a3 = fmaf(hv3, wa, a3);
                b0 = fmaf(hv0, wb, b0); b1 = fmaf(hv1, wb, b1);
                b2 = fmaf(hv2, wb, b2); b3 = fmaf(hv3, wb, b3);
            }
        }
        size_t base = (size_t)(n0 + nl) * TSL + t;
        g_T[base          ] = a0;  g_T[base           + 288] = b0;
        g_T[base +     TSL] = a1;  g_T[base +     TSL + 288] = b1;
        g_T[base + 2 * TSL] = a2;  g_T[base + 2 * TSL + 288] = b2;
        g_T[base + 3 * TSL] = a3;  g_T[base + 3 * TSL + 288] = b3;
    }
}

// ---------------------------------------------------------------------------
// msgA: edge-parallel over SRC-SORTED positions. Consecutive warps share src
// T-rows -> L1-served gather (L2 sees ~43.5MB unique instead of 348MB).
// Message stored to its dst-sorted slot: plain 128B store, zero atomics.
// ---------------------------------------------------------------------------
__global__ void msgAKernel(const void* __restrict__ ef) {
    int bf = g_flag;
    int pos = blockIdx.x * 8 + (threadIdx.x >> 5);   // grid exact: pos < EE
    int lane = threadIdx.x & 31;

    int e = g_perm[pos];                             // warp-uniform loads
    int s = g_psrc[pos];
    int q = g_outq[pos];

    float efv = (lane < 16) ? ldF(ef, (long)e * 16 + lane, bf) : 0.0f;

    const float* Trow = g_T + (size_t)s * TSL;
    float t[17];
#pragma unroll
    for (int dd = 0; dd < 16; dd++) t[dd] = Trow[dd * 32 + lane];
    t[16] = Trow[512 + lane];                        // bias slice

    float acc = t[16];
#pragma unroll
    for (int dd = 0; dd < 16; dd++) {
        float c = __shfl_sync(0xffffffffu, efv, dd);
        acc = fmaf(c, t[dd], acc);
    }
    g_msg[(size_t)q * HD + lane] = acc;
}

// ---------------------------------------------------------------------------
// msgB: warp per DST node; sums its contiguous dst-sorted run. Fully writes
// g_m (zero for degree-0 nodes) -> no zeroing pass, no atomics.
// ---------------------------------------------------------------------------
__global__ void msgBKernel() {
    int n = blockIdx.x * 8 + (threadIdx.x >> 5);     // grid exact: n < NN
    int lane = threadIdx.x & 31;

    int base = g_off_dst[n];
    int cnt  = g_cnt_dst[n];
    float acc = 0.0f;
    for (int i = 0; i < cnt; i++)
        acc += g_msg[(size_t)(base + i) * HD + lane];
    g_m[n * 32 + lane] = acc;
}

// ---------------------------------------------------------------------------
// GRUCell (torch layout r,z,n). Warp per node; 6 independent FMA chains.
// ---------------------------------------------------------------------------
__global__ void gruKernel(const void* __restrict__ W_ih, const void* __restrict__ W_hh,
                          const void* __restrict__ b_ih, const void* __restrict__ b_hh,
                          void* __restrict__ outp, int finalStep) {
    __shared__ float Wi[96 * 33];
    __shared__ float Wh[96 * 33];
    int bf = g_flag;
    int tid = threadIdx.x;
    for (int i = tid; i < 96 * 32; i += 256) {
        int j = i >> 5, k = i & 31;
        Wi[j * 33 + k] = ldF(W_ih, i, bf);
        Wh[j * 33 + k] = ldF(W_hh, i, bf);
    }
    __syncthreads();

    int n = blockIdx.x * 8 + (tid >> 5);             // grid exact: n < NN
    int lane = tid & 31;

    float mv = g_m[n * 32 + lane];
    float hv = g_h[n * 32 + lane];

    float gi0 = ldF(b_ih, lane, bf), gi1 = ldF(b_ih, 32 + lane, bf), gi2 = ldF(b_ih, 64 + lane, bf);
    float gh0 = ldF(b_hh, lane, bf), gh1 = ldF(b_hh, 32 + lane, bf), gh2 = ldF(b_hh, 64 + lane, bf);
#pragma unroll
    for (int k = 0; k < 32; k++) {
        float mk = __shfl_sync(0xffffffffu, mv, k);
        float hk = __shfl_sync(0xffffffffu, hv, k);
        gi0 = fmaf(mk, Wi[lane * 33 + k],        gi0);
        gi1 = fmaf(mk, Wi[(32 + lane) * 33 + k], gi1);
        gi2 = fmaf(mk, Wi[(64 + lane) * 33 + k], gi2);
        gh0 = fmaf(hk, Wh[lane * 33 + k],        gh0);
        gh1 = fmaf(hk, Wh[(32 + lane) * 33 + k], gh1);
        gh2 = fmaf(hk, Wh[(64 + lane) * 33 + k], gh2);
    }
    float r  = 1.0f / (1.0f + __expf(-(gi0 + gh0)));
    float z  = 1.0f / (1.0f + __expf(-(gi1 + gh1)));
    float nn = tanhf(gi2 + r * gh2);
    float hnew = (1.0f - z) * nn + z * hv;

    if (finalStep) {
        if (bf) ((__nv_bfloat16*)outp)[n * 32 + lane] = __float2bfloat16(hnew);
        else    ((float*)outp)[n * 32 + lane] = hnew;
    } else {
        ((float*)outp)[n * 32 + lane] = hnew;        // g_h
    }
}

// ---------------------------------------------------------------------------
// Host: size-based binding (element counts) with positional fallback.
// ---------------------------------------------------------------------------
static int findBySz(const int* sizes, int n, long target, int occurrence) {
    int c = 0;
    for (int i = 0; i < n; i++)
        if ((long)sizes[i] == target) { if (c == occurrence) return i; c++; }
    return -1;
}

extern "C" void kernel_launch(void* const* d_in, const int* in_sizes, int n_in,
                              void* d_out, int out_size) {
    int i_nf = findBySz(in_sizes, n_in, (long)NN * ND, 0);
    int i_ei = findBySz(in_sizes, n_in, (long)2 * EE, 0);
    int i_ef = findBySz(in_sizes, n_in, (long)EE * ED, 0);
    int i_Wn = findBySz(in_sizes, n_in, (long)HD * ND, 0);
    int i_bn = findBySz(in_sizes, n_in, (long)HD, 0);
    int i_We = findBySz(in_sizes, n_in, (long)HD * HD * ED, 0);
    int i_be = findBySz(in_sizes, n_in, (long)HD * HD, 0);
    int i_g0 = findBySz(in_sizes, n_in, (long)3 * HD * HD, 0);
    int i_g1 = findBySz(in_sizes, n_in, (long)3 * HD * HD, 1);
    int i_q0 = findBySz(in_sizes, n_in, (long)3 * HD, 0);
    int i_q1 = findBySz(in_sizes, n_in, (long)3 * HD, 1);

    if (i_nf < 0 || i_ei < 0 || i_ef < 0 || i_Wn < 0 || i_bn < 0 ||
        i_We < 0 || i_be < 0 || i_g0 < 0 || i_g1 < 0 || i_q0 < 0 || i_q1 < 0) {
        i_nf = 0; i_ei = 1; i_ef = 2; i_Wn = 3; i_bn = 4;
        i_We = 5; i_be = 6; i_g0 = 7; i_g1 = 8; i_q0 = 9; i_q1 = 10;
    }

    const void* node_feat  = d_in[i_nf];
    const int*  edge_index = (const int*)d_in[i_ei];
    const void* edge_feat  = d_in[i_ef];
    const void* W_np       = d_in[i_Wn];
    const void* b_np       = d_in[i_bn];
    const void* W_e        = d_in[i_We];
    const void* b_e        = d_in[i_be];
    const void* W_ih       = d_in[i_g0];             // signature order: W_ih first
    const void* W_hh       = d_in[i_g1];
    const void* b_ih       = d_in[i_q0];
    const void* b_hh       = d_in[i_q1];

    const int* srcIdx = edge_index;                  // edge_index[0, :]
    const int* dstIdx = edge_index + EE;             // edge_index[1, :]

    static void* g_h_addr = nullptr;
    if (!g_h_addr) (void)cudaGetSymbolAddress(&g_h_addr, g_h);

    // --- setup (captured; deterministic work) ---
    detectKernel<<<1, 32>>>((const unsigned int*)node_feat);
    buildW2Kernel<<<(TSL * HD + 255) / 256, 256>>>(W_e, b_e);
    zeroCntKernel<<<(NN + 255) / 256, 256>>>();
    histKernel<<<(EE + 255) / 256, 256>>>(srcIdx, dstIdx);
    scanKernel<<<1, 1024>>>();
    scatterIdxKernel<<<(EE + 255) / 256, 256>>>(srcIdx, dstIdx);
    nodeProjKernel<<<NN / 8, 256>>>(node_feat, W_np, b_np);

    // --- 3 propagation steps ---
    for (int step = 0; step < 3; step++) {
        compTKernel<<<296, 288>>>();
        msgAKernel<<<EE / 8, 256>>>(edge_feat);
        msgBKernel<<<NN / 8, 256>>>();
        int fin = (step == 2);
        void* hout = fin ? d_out : g_h_addr;
        gruKernel<<<NN / 8, 256>>>(W_ih, W_hh, b_ih, b_hh, hout, fin);
    }
}

// round 10
// speedup vs baseline: 1.2186x; 1.2186x over previous
#include <cuda_runtime.h>
#include <cuda_bf16.h>

// Problem constants (FIXED by reference): N=20000, E=160000, NODE_DIM=64, EDGE_DIM=16, H=32, STEPS=3
#define NN     20000
#define EE     160000
#define HD     32
#define ND     64
#define ED     16
#define TSL    576          // padded T row stride: 18 slices of 32 (16 edge-dims + bias + pad)

// Scratch (allocation-free rule: __device__ globals)
__device__ int   g_flag;                     // 1 = float inputs are bf16, 0 = fp32
__device__ float g_h [NN * HD];              // node hidden state (fp32 internal)
__device__ float g_m [NN * HD];              // aggregated messages
__device__ float g_T [NN * TSL];             // per-node tensor (46 MB, L2-resident)
__device__ float g_W2[TSL * HD];             // reshaped edge weight (rows >= 544 zero)
// src-CSR scratch (rebuilt every replay; deterministic)
__device__ int   g_cnt_src[NN];
__device__ int   g_off_src[NN];
__device__ int   g_cur_src[NN];
__device__ int   g_p    [EE];                // edge -> src-sorted position
__device__ int   g_psrc [EE];                // position -> src node
__device__ int   g_pdst [EE];                // position -> dst node
__device__ float g_efs  [EE * ED];           // edge_feat permuted to src order (fp32)

namespace {
struct EagerLoad {                            // materialize device globals at process start
    EagerLoad() { void* p = nullptr; (void)cudaGetSymbolAddress(&p, g_h); }
};
EagerLoad eager_load_;
}

// Dtype-agnostic float load (branch is warp-uniform on g_flag).
__device__ __forceinline__ float ldF(const void* p, long i, int bf) {
    return bf ? __bfloat162float(((const __nv_bfloat16*)p)[i])
              : ((const float*)p)[i];
}

// ---------------------------------------------------------------------------
// Detect input dtype from node_feat bit patterns (see R4 notes).
// ---------------------------------------------------------------------------
__global__ void detectKernel(const unsigned int* __restrict__ nf) {
    int lane = threadIdx.x;
    int cnt = 0;
    for (int i = lane; i < 1024; i += 32) {
        unsigned int e = (nf[i] >> 7) & 0xFF;
        cnt += (e >= 110 && e <= 140) ? 1 : 0;
    }
#pragma unroll
    for (int o = 16; o > 0; o >>= 1) cnt += __shfl_down_sync(0xffffffffu, cnt, o);
    if (lane == 0) g_flag = (cnt > 512) ? 1 : 0;
}

// ---------------------------------------------------------------------------
// src-CSR setup: histogram -> scan -> slot assignment -> ef permute.
// ---------------------------------------------------------------------------
__global__ void zeroCntKernel() {
    int i = blockIdx.x * 256 + threadIdx.x;
    if (i < NN) g_cnt_src[i] = 0;
}

__global__ void histKernel(const int* __restrict__ src) {
    int e = blockIdx.x * 256 + threadIdx.x;
    if (e >= EE) return;
    int s = src[e]; if ((unsigned)s >= (unsigned)NN) s = 0;
    atomicAdd(&g_cnt_src[s], 1);
}

// Exclusive prefix scan of g_cnt_src (1 block, 1024 threads, 20 items each).
__global__ void scanKernel() {
    __shared__ int part[1024];
    int t = threadIdx.x;
    int base = t * 20;                               // 1024*20 >= NN
    int s = 0;
    for (int i = 0; i < 20; i++) {
        int idx = base + i;
        s += (idx < NN) ? g_cnt_src[idx] : 0;
    }
    part[t] = s;
    __syncthreads();
    for (int d = 1; d < 1024; d <<= 1) {             // Hillis-Steele inclusive
        int v = (t >= d) ? part[t - d] : 0;
        __syncthreads();
        part[t] += v;
        __syncthreads();
    }
    int run = (t > 0) ? part[t - 1] : 0;             // exclusive base for chunk
    for (int i = 0; i < 20; i++) {
        int idx = base + i;
        if (idx < NN) { g_off_src[idx] = run; run += g_cnt_src[idx]; g_cur_src[idx] = 0; }
    }
}

__global__ void scatterIdxKernel(const int* __restrict__ src, const int* __restrict__ dst) {
    int e = blockIdx.x * 256 + threadIdx.x;
    if (e >= EE) return;
    int s = src[e]; if ((unsigned)s >= (unsigned)NN) s = 0;
    int d = dst[e]; if ((unsigned)d >= (unsigned)NN) d = 0;
    int p = g_off_src[s] + atomicAdd(&g_cur_src[s], 1);
    g_p[e]    = p;
    g_psrc[p] = s;
    g_pdst[p] = d;
}

// Permute edge_feat into src order (fp32). Coalesced read; scattered 64B write.
__global__ void scatterEfKernel(const void* __restrict__ ef) {
    int bf = g_flag;
    long i = (long)blockIdx.x * 256 + threadIdx.x;   // i = e*16 + d
    if (i >= (long)EE * ED) return;
    int e = (int)(i >> 4), dd = (int)(i & 15);
    g_efs[(long)g_p[e] * ED + dd] = ldF(ef, i, bf);
}

// ---------------------------------------------------------------------------
// Build W2: W2[(d*32+h)*32+k] = W_e[(h*32+k)*16+d]; slice 16 = b_e; 17 = pad 0.
// ---------------------------------------------------------------------------
__global__ void buildW2Kernel(const void* __restrict__ We, const void* __restrict__ be) {
    int bf = g_flag;
    int i = blockIdx.x * 256 + threadIdx.x;
    if (i >= TSL * HD) return;
    int j = i >> 5, k = i & 31;
    int d = j >> 5, h = j & 31;
    float v = 0.0f;
    if (d < 16)       v = ldF(We, (h * 32 + k) * 16 + d, bf);
    else if (d == 16) v = ldF(be, h * 32 + k, bf);
    g_W2[i] = v;
}

// ---------------------------------------------------------------------------
// h = node_feat @ W_np^T + b_np ; also zero g_m. Warp per node.
// ---------------------------------------------------------------------------
__global__ void nodeProjKernel(const void* __restrict__ nf, const void* __restrict__ W,
                               const void* __restrict__ b) {
    __shared__ float Ws[32 * 65];
    int bf = g_flag;
    int tid = threadIdx.x;
    for (int i = tid; i < 32 * 64; i += 256)
        Ws[(i >> 6) * 65 + (i & 63)] = ldF(W, i, bf);
    __syncthreads();

    g_m[blockIdx.x * 256 + tid] = 0.0f;              // exact cover: 2500*256 == N*H

    int n = blockIdx.x * 8 + (tid >> 5);
    int lane = tid & 31;

    float v0 = ldF(nf, n * 64 + lane, bf);
    float v1 = ldF(nf, n * 64 + 32 + lane, bf);
    float acc = ldF(b, lane, bf);
#pragma unroll
    for (int k = 0; k < 32; k++) {
        float a0 = __shfl_sync(0xffffffffu, v0, k);
        float a1 = __shfl_sync(0xffffffffu, v1, k);
        acc = fmaf(a0, Ws[lane * 65 + k], acc);
        acc = fmaf(a1, Ws[lane * 65 + 32 + k], acc);
    }
    g_h[n * 32 + lane] = acc;
}

// ---------------------------------------------------------------------------
// T[n, j] = sum_k W2[j][k] * h[n][k]
// 296 blocks x 68 nodes (one uniform wave), 288 threads, 2 W2 rows + 4-node ILP.
// (Frozen from R8: 41.9us, smem-crossbar bound.)
// ---------------------------------------------------------------------------
__global__ void __launch_bounds__(288, 2) compTKernel() {
    __shared__ __align__(16) float hs[68][32];
    int t = threadIdx.x;                              // 0..287
    int n0 = blockIdx.x * 68;

    float w0[32], w1[32];
#pragma unroll
    for (int k = 0; k < 32; k++) {
        w0[k] = g_W2[t * 32 + k];
        w1[k] = g_W2[(t + 288) * 32 + k];
    }

    for (int i = t; i < 68 * 32; i += 288) {
        int n = n0 + (i >> 5);
        hs[i >> 5][i & 31] = (n < NN) ? g_h[n * 32 + (i & 31)] : 0.0f;
    }
    __syncthreads();

    int nend = NN - n0;
    if (nend > 68) nend = 68;
    for (int nl = 0; nl < nend; nl += 4) {            // nend % 4 == 0 always
        const float4* p0 = reinterpret_cast<const float4*>(hs[nl + 0]);
        const float4* p1 = reinterpret_cast<const float4*>(hs[nl + 1]);
        const float4* p2 = reinterpret_cast<const float4*>(hs[nl + 2]);
        const float4* p3 = reinterpret_cast<const float4*>(hs[nl + 3]);
        float a0 = 0.f, a1 = 0.f, a2 = 0.f, a3 = 0.f;  // j = t
        float b0 = 0.f, b1 = 0.f, b2 = 0.f, b3 = 0.f;  // j = t + 288
#pragma unroll
        for (int kk = 0; kk < 8; kk++) {
            float4 h0 = p0[kk], h1 = p1[kk], h2 = p2[kk], h3 = p3[kk];
#pragma unroll
            for (int q = 0; q < 4; q++) {
                float hv0 = (&h0.x)[q], hv1 = (&h1.x)[q];
                float hv2 = (&h2.x)[q], hv3 = (&h3.x)[q];
                float wa = w0[kk * 4 + q], wb = w1[kk * 4 + q];
                a0 = fmaf(hv0, wa, a0); a1 = fmaf(hv1, wa, a1);
                a2 = fmaf(hv2, wa, a2); a3 = fmaf(hv3, wa, a3);
                b0 = fmaf(hv0, wb, b0); b1 = fmaf(hv1, wb, b1);
                b2 = fmaf(hv2, wb, b2); b3 = fmaf(hv3, wb, b3);
            }
        }
        size_t base = (size_t)(n0 + nl) * TSL + t;
        g_T[base          ] = a0;  g_T[base           + 288] = b0;
        g_T[base +     TSL] = a1;  g_T[base +     TSL + 288] = b1;
        g_T[base + 2 * TSL] = a2;  g_T[base + 2 * TSL + 288] = b2;
        g_T[base + 3 * TSL] = a3;  g_T[base + 3 * TSL + 288] = b3;
    }
}

// ---------------------------------------------------------------------------
// msg: warp per SRC-SORTED position. Consecutive warps share the same src
// T-row -> gather served from L1 (L2 sees ~43.5MB unique, was 348MB).
// ef permuted to src order -> coalesced. Scatter = R8's proven atomicAdd.
// ---------------------------------------------------------------------------
__global__ void msgKernel() {
    int pos = blockIdx.x * 8 + (threadIdx.x >> 5);   // grid exact: pos < EE
    int lane = threadIdx.x & 31;

    int s = g_psrc[pos];                             // warp-uniform
    int d = g_pdst[pos];                             // warp-uniform
    float efv = (lane < 16) ? g_efs[(long)pos * ED + lane] : 0.0f;

    const float* Trow = g_T + (size_t)s * TSL;
    float t[17];
#pragma unroll
    for (int dd = 0; dd < 16; dd++) t[dd] = Trow[dd * 32 + lane];    // batched, L1-hit
    t[16] = Trow[512 + lane];                                        // bias slice

    float acc = t[16];
#pragma unroll
    for (int dd = 0; dd < 16; dd++) {
        float c = __shfl_sync(0xffffffffu, efv, dd);
        acc = fmaf(c, t[dd], acc);
    }
    atomicAdd(&g_m[d * 32 + lane], acc);
}

// ---------------------------------------------------------------------------
// GRUCell (torch layout r,z,n). Warp per node; 6 independent FMA chains.
// Final step writes d_out in detected dtype. Re-zeroes g_m for replay.
// ---------------------------------------------------------------------------
__global__ void gruKernel(const void* __restrict__ W_ih, const void* __restrict__ W_hh,
                          const void* __restrict__ b_ih, const void* __restrict__ b_hh,
                          void* __restrict__ outp, int finalStep) {
    __shared__ float Wi[96 * 33];
    __shared__ float Wh[96 * 33];
    int bf = g_flag;
    int tid = threadIdx.x;
    for (int i = tid; i < 96 * 32; i += 256) {
        int j = i >> 5, k = i & 31;
        Wi[j * 33 + k] = ldF(W_ih, i, bf);
        Wh[j * 33 + k] = ldF(W_hh, i, bf);
    }
    __syncthreads();

    int n = blockIdx.x * 8 + (tid >> 5);             // grid exact: n < NN
    int lane = tid & 31;

    float mv = g_m[n * 32 + lane];
    float hv = g_h[n * 32 + lane];
    g_m[n * 32 + lane] = 0.0f;                       // reset for next step / replay

    float gi0 = ldF(b_ih, lane, bf), gi1 = ldF(b_ih, 32 + lane, bf), gi2 = ldF(b_ih, 64 + lane, bf);
    float gh0 = ldF(b_hh, lane, bf), gh1 = ldF(b_hh, 32 + lane, bf), gh2 = ldF(b_hh, 64 + lane, bf);
#pragma unroll
    for (int k = 0; k < 32; k++) {
        float mk = __shfl_sync(0xffffffffu, mv, k);
        float hk = __shfl_sync(0xffffffffu, hv, k);
        gi0 = fmaf(mk, Wi[lane * 33 + k],        gi0);
        gi1 = fmaf(mk, Wi[(32 + lane) * 33 + k], gi1);
        gi2 = fmaf(mk, Wi[(64 + lane) * 33 + k], gi2);
        gh0 = fmaf(hk, Wh[lane * 33 + k],        gh0);
        gh1 = fmaf(hk, Wh[(32 + lane) * 33 + k], gh1);
        gh2 = fmaf(hk, Wh[(64 + lane) * 33 + k], gh2);
    }
    float r  = 1.0f / (1.0f + __expf(-(gi0 + gh0)));
    float z  = 1.0f / (1.0f + __expf(-(gi1 + gh1)));
    float nn = tanhf(gi2 + r * gh2);
    float hnew = (1.0f - z) * nn + z * hv;

    if (finalStep) {
        if (bf) ((__nv_bfloat16*)outp)[n * 32 + lane] = __float2bfloat16(hnew);
        else    ((float*)outp)[n * 32 + lane] = hnew;
    } else {
        ((float*)outp)[n * 32 + lane] = hnew;        // g_h
    }
}

// ---------------------------------------------------------------------------
// Host: size-based binding (element counts) with positional fallback.
// ---------------------------------------------------------------------------
static int findBySz(const int* sizes, int n, long target, int occurrence) {
    int c = 0;
    for (int i = 0; i < n; i++)
        if ((long)sizes[i] == target) { if (c == occurrence) return i; c++; }
    return -1;
}

extern "C" void kernel_launch(void* const* d_in, const int* in_sizes, int n_in,
                              void* d_out, int out_size) {
    int i_nf = findBySz(in_sizes, n_in, (long)NN * ND, 0);
    int i_ei = findBySz(in_sizes, n_in, (long)2 * EE, 0);
    int i_ef = findBySz(in_sizes, n_in, (long)EE * ED, 0);
    int i_Wn = findBySz(in_sizes, n_in, (long)HD * ND, 0);
    int i_bn = findBySz(in_sizes, n_in, (long)HD, 0);
    int i_We = findBySz(in_sizes, n_in, (long)HD * HD * ED, 0);
    int i_be = findBySz(in_sizes, n_in, (long)HD * HD, 0);
    int i_g0 = findBySz(in_sizes, n_in, (long)3 * HD * HD, 0);
    int i_g1 = findBySz(in_sizes, n_in, (long)3 * HD * HD, 1);
    int i_q0 = findBySz(in_sizes, n_in, (long)3 * HD, 0);
    int i_q1 = findBySz(in_sizes, n_in, (long)3 * HD, 1);

    if (i_nf < 0 || i_ei < 0 || i_ef < 0 || i_Wn < 0 || i_bn < 0 ||
        i_We < 0 || i_be < 0 || i_g0 < 0 || i_g1 < 0 || i_q0 < 0 || i_q1 < 0) {
        i_nf = 0; i_ei = 1; i_ef = 2; i_Wn = 3; i_bn = 4;
        i_We = 5; i_be = 6; i_g0 = 7; i_g1 = 8; i_q0 = 9; i_q1 = 10;
    }

    const void* node_feat  = d_in[i_nf];
    const int*  edge_index = (const int*)d_in[i_ei];
    const void* edge_feat  = d_in[i_ef];
    const void* W_np       = d_in[i_Wn];
    const void* b_np       = d_in[i_bn];
    const void* W_e        = d_in[i_We];
    const void* b_e        = d_in[i_be];
    const void* W_ih       = d_in[i_g0];             // signature order: W_ih first
    const void* W_hh       = d_in[i_g1];
    const void* b_ih       = d_in[i_q0];
    const void* b_hh       = d_in[i_q1];

    const int* srcIdx = edge_index;                  // edge_index[0, :]
    const int* dstIdx = edge_index + EE;             // edge_index[1, :]

    static void* g_h_addr = nullptr;
    if (!g_h_addr) (void)cudaGetSymbolAddress(&g_h_addr, g_h);

    // --- setup (captured; deterministic) ---
    detectKernel<<<1, 32>>>((const unsigned int*)node_feat);
    buildW2Kernel<<<(TSL * HD + 255) / 256, 256>>>(W_e, b_e);
    zeroCntKernel<<<(NN + 255) / 256, 256>>>();
    histKernel<<<(EE + 255) / 256, 256>>>(srcIdx);
    scanKernel<<<1, 1024>>>();
    scatterIdxKernel<<<(EE + 255) / 256, 256>>>(srcIdx, dstIdx);
    scatterEfKernel<<<(int)(((long)EE * ED + 255) / 256), 256>>>(edge_feat);
    nodeProjKernel<<<NN / 8, 256>>>(node_feat, W_np, b_np);

    // --- 3 propagation steps ---
    for (int step = 0; step < 3; step++) {
        compTKernel<<<296, 288>>>();
        msgKernel<<<EE / 8, 256>>>();
        int fin = (step == 2);
        void* hout = fin ? d_out : g_h_addr;
        gruKernel<<<NN / 8, 256>>>(W_ih, W_hh, b_ih, b_hh, hout, fin);
    }
}

// round 11
// speedup vs baseline: 1.4953x; 1.2271x over previous
#include <cuda_runtime.h>
#include <cuda_bf16.h>

// Problem constants (FIXED by reference): N=20000, E=160000, NODE_DIM=64, EDGE_DIM=16, H=32, STEPS=3
#define NN     20000
#define EE     160000
#define HD     32
#define ND     64
#define ED     16
#define TSL    576          // padded T row stride: 18 slices of 32 (16 edge-dims + bias + pad)

// Scratch (allocation-free rule: __device__ globals)
__device__ int   g_flag;                     // 1 = float inputs are bf16, 0 = fp32
__device__ float g_h [NN * HD];              // node hidden state (fp32 internal)
__device__ float g_m [NN * HD];              // aggregated messages
__device__ float g_T [NN * TSL];             // per-node tensor (46 MB, L2-resident)
__device__ float g_W2[TSL * HD];             // reshaped edge weight (rows >= 544 zero)

namespace {
struct EagerLoad {                            // materialize device globals at process start
    EagerLoad() { void* p = nullptr; (void)cudaGetSymbolAddress(&p, g_h); }
};
EagerLoad eager_load_;
}

// Dtype-agnostic float load (branch is warp-uniform on flag).
__device__ __forceinline__ float ldF(const void* p, long i, int bf) {
    return bf ? __bfloat162float(((const __nv_bfloat16*)p)[i])
              : ((const float*)p)[i];
}

// ---------------------------------------------------------------------------
// buildW2 + dtype detection (merged so msgKernel is the 4th launch -> profiled).
// Every block self-detects bf16-ness from node_feat bit patterns (see R4);
// block 0 also publishes g_flag for the other kernels.
// W2[(d*32+h)*32+k] = W_e[(h*32+k)*16+d]; slice 16 = b_e; slice 17 = pad 0.
// ---------------------------------------------------------------------------
__global__ void buildW2Kernel(const unsigned int* __restrict__ nf,
                              const void* __restrict__ We, const void* __restrict__ be) {
    __shared__ int sflag;
    int tid = threadIdx.x;
    if (tid < 32) {
        int cnt = 0;
        for (int i = tid; i < 1024; i += 32) {
            unsigned int e = (nf[i] >> 7) & 0xFF;
            cnt += (e >= 110 && e <= 140) ? 1 : 0;
        }
#pragma unroll
        for (int o = 16; o > 0; o >>= 1) cnt += __shfl_down_sync(0xffffffffu, cnt, o);
        if (tid == 0) {
            sflag = (cnt > 512) ? 1 : 0;
            if (blockIdx.x == 0) g_flag = sflag;
        }
    }
    __syncthreads();
    int bf = sflag;

    int i = blockIdx.x * 256 + tid;
    if (i >= TSL * HD) return;
    int j = i >> 5, k = i & 31;
    int d = j >> 5, h = j & 31;
    float v = 0.0f;
    if (d < 16)       v = ldF(We, (h * 32 + k) * 16 + d, bf);
    else if (d == 16) v = ldF(be, h * 32 + k, bf);
    g_W2[i] = v;
}

// ---------------------------------------------------------------------------
// h = node_feat @ W_np^T + b_np ; also zero g_m. Warp per node.
// ---------------------------------------------------------------------------
__global__ void nodeProjKernel(const void* __restrict__ nf, const void* __restrict__ W,
                               const void* __restrict__ b) {
    __shared__ float Ws[32 * 65];
    int bf = g_flag;
    int tid = threadIdx.x;
    for (int i = tid; i < 32 * 64; i += 256)
        Ws[(i >> 6) * 65 + (i & 63)] = ldF(W, i, bf);
    __syncthreads();

    g_m[blockIdx.x * 256 + tid] = 0.0f;              // exact cover: 2500*256 == N*H

    int n = blockIdx.x * 8 + (tid >> 5);
    int lane = tid & 31;

    float v0 = ldF(nf, n * 64 + lane, bf);
    float v1 = ldF(nf, n * 64 + 32 + lane, bf);
    float acc = ldF(b, lane, bf);
#pragma unroll
    for (int k = 0; k < 32; k++) {
        float a0 = __shfl_sync(0xffffffffu, v0, k);
        float a1 = __shfl_sync(0xffffffffu, v1, k);
        acc = fmaf(a0, Ws[lane * 65 + k], acc);
        acc = fmaf(a1, Ws[lane * 65 + 32 + k], acc);
    }
    g_h[n * 32 + lane] = acc;
}

// ---------------------------------------------------------------------------
// T[n, j] = sum_k W2[j][k] * h[n][k]
// 296 blocks x 68 nodes (one uniform wave), 288 threads, 2 W2 rows + 4-node ILP.
// (Frozen from R8: 41.9us, smem-crossbar bound.)
// ---------------------------------------------------------------------------
__global__ void __launch_bounds__(288, 2) compTKernel() {
    __shared__ __align__(16) float hs[68][32];
    int t = threadIdx.x;                              // 0..287
    int n0 = blockIdx.x * 68;

    float w0[32], w1[32];
#pragma unroll
    for (int k = 0; k < 32; k++) {
        w0[k] = g_W2[t * 32 + k];
        w1[k] = g_W2[(t + 288) * 32 + k];
    }

    for (int i = t; i < 68 * 32; i += 288) {
        int n = n0 + (i >> 5);
        hs[i >> 5][i & 31] = (n < NN) ? g_h[n * 32 + (i & 31)] : 0.0f;
    }
    __syncthreads();

    int nend = NN - n0;
    if (nend > 68) nend = 68;
    for (int nl = 0; nl < nend; nl += 4) {            // nend % 4 == 0 always
        const float4* p0 = reinterpret_cast<const float4*>(hs[nl + 0]);
        const float4* p1 = reinterpret_cast<const float4*>(hs[nl + 1]);
        const float4* p2 = reinterpret_cast<const float4*>(hs[nl + 2]);
        const float4* p3 = reinterpret_cast<const float4*>(hs[nl + 3]);
        float a0 = 0.f, a1 = 0.f, a2 = 0.f, a3 = 0.f;  // j = t
        float b0 = 0.f, b1 = 0.f, b2 = 0.f, b3 = 0.f;  // j = t + 288
#pragma unroll
        for (int kk = 0; kk < 8; kk++) {
            float4 h0 = p0[kk], h1 = p1[kk], h2 = p2[kk], h3 = p3[kk];
#pragma unroll
            for (int q = 0; q < 4; q++) {
                float hv0 = (&h0.x)[q], hv1 = (&h1.x)[q];
                float hv2 = (&h2.x)[q], hv3 = (&h3.x)[q];
                float wa = w0[kk * 4 + q], wb = w1[kk * 4 + q];
                a0 = fmaf(hv0, wa, a0); a1 = fmaf(hv1, wa, a1);
                a2 = fmaf(hv2, wa, a2); a3 = fmaf(hv3, wa, a3);
                b0 = fmaf(hv0, wb, b0); b1 = fmaf(hv1, wb, b1);
                b2 = fmaf(hv2, wb, b2); b3 = fmaf(hv3, wb, b3);
            }
        }
        size_t base = (size_t)(n0 + nl) * TSL + t;
        g_T[base          ] = a0;  g_T[base           + 288] = b0;
        g_T[base +     TSL] = a1;  g_T[base +     TSL + 288] = b1;
        g_T[base + 2 * TSL] = a2;  g_T[base + 2 * TSL + 288] = b2;
        g_T[base + 3 * TSL] = a3;  g_T[base + 3 * TSL + 288] = b3;
    }
}

// ---------------------------------------------------------------------------
// msg: 4 edges per warp, 8 lanes per edge, each lane owns a 4-channel quad.
//   msg[e, 4q..4q+3] = T4[src][16][q] + sum_d ef[e,d] * T4[src][d][q]
// T loads are float4 (8 lanes x 16B = 128B/row, coalesced as before).
// Scatter via red.global.add.v4.f32: 4x fewer REDG lane-ops than scalar
// atomicAdd (R10 showed msg is scatter/issue-co-bound, not gather-bound).
// Grid: 5000 blocks x 256 thr = 40000 warps x 4 edges = 160000, exact.
// ---------------------------------------------------------------------------
__global__ void msgKernel(const int* __restrict__ src, const int* __restrict__ dst,
                          const void* __restrict__ ef) {
    int bf = g_flag;
    int lane = threadIdx.x & 31;
    int g    = lane >> 3;                            // edge slot within warp (0..3)
    int sub  = lane & 7;                             // channel quad (0..7)
    int e = (blockIdx.x * (256 / 32) + (threadIdx.x >> 5)) * 4 + g;   // e < EE exact

    int s = src[e]; if ((unsigned)s >= (unsigned)NN) s = 0;
    int d = dst[e]; if ((unsigned)d >= (unsigned)NN) d = 0;

    // ef[e][sub*2], ef[e][sub*2+1] per lane -> 16 coeffs per edge across 8 lanes
    float f0 = ldF(ef, (long)e * 16 + sub * 2,     bf);
    float f1 = ldF(ef, (long)e * 16 + sub * 2 + 1, bf);

    const float* Trow = g_T + (size_t)s * TSL;
    float4 t4[17];
#pragma unroll
    for (int dd = 0; dd < 16; dd++)
        t4[dd] = *reinterpret_cast<const float4*>(Trow + dd * 32 + sub * 4);
    t4[16] = *reinterpret_cast<const float4*>(Trow + 512 + sub * 4);   // bias quad

    float4 acc = t4[16];
#pragma unroll
    for (int dd = 0; dd < 16; dd++) {
        int sl = g * 8 + (dd >> 1);
        float c = __shfl_sync(0xffffffffu, (dd & 1) ? f1 : f0, sl);
        acc.x = fmaf(c, t4[dd].x, acc.x);
        acc.y = fmaf(c, t4[dd].y, acc.y);
        acc.z = fmaf(c, t4[dd].z, acc.z);
        acc.w = fmaf(c, t4[dd].w, acc.w);
    }

    float* outp = &g_m[d * 32 + sub * 4];            // 16B-aligned
    asm volatile("red.global.add.v4.f32 [%0], {%1, %2, %3, %4};"
                 :: "l"(outp), "f"(acc.x), "f"(acc.y), "f"(acc.z), "f"(acc.w)
                 : "memory");
}

// ---------------------------------------------------------------------------
// GRUCell (torch layout r,z,n). Warp per node; 6 independent FMA chains.
// Final step writes d_out in detected dtype. Re-zeroes g_m for replay.
// ---------------------------------------------------------------------------
__global__ void gruKernel(const void* __restrict__ W_ih, const void* __restrict__ W_hh,
                          const void* __restrict__ b_ih, const void* __restrict__ b_hh,
                          void* __restrict__ outp, int finalStep) {
    __shared__ float Wi[96 * 33];
    __shared__ float Wh[96 * 33];
    int bf = g_flag;
    int tid = threadIdx.x;
    for (int i = tid; i < 96 * 32; i += 256) {
        int j = i >> 5, k = i & 31;
        Wi[j * 33 + k] = ldF(W_ih, i, bf);
        Wh[j * 33 + k] = ldF(W_hh, i, bf);
    }
    __syncthreads();

    int n = blockIdx.x * 8 + (tid >> 5);             // grid exact: n < NN
    int lane = tid & 31;

    float mv = g_m[n * 32 + lane];
    float hv = g_h[n * 32 + lane];
    g_m[n * 32 + lane] = 0.0f;                       // reset for next step / replay

    float gi0 = ldF(b_ih, lane, bf), gi1 = ldF(b_ih, 32 + lane, bf), gi2 = ldF(b_ih, 64 + lane, bf);
    float gh0 = ldF(b_hh, lane, bf), gh1 = ldF(b_hh, 32 + lane, bf), gh2 = ldF(b_hh, 64 + lane, bf);
#pragma unroll
    for (int k = 0; k < 32; k++) {
        float mk = __shfl_sync(0xffffffffu, mv, k);
        float hk = __shfl_sync(0xffffffffu, hv, k);
        gi0 = fmaf(mk, Wi[lane * 33 + k],        gi0);
        gi1 = fmaf(mk, Wi[(32 + lane) * 33 + k], gi1);
        gi2 = fmaf(mk, Wi[(64 + lane) * 33 + k], gi2);
        gh0 = fmaf(hk, Wh[lane * 33 + k],        gh0);
        gh1 = fmaf(hk, Wh[(32 + lane) * 33 + k], gh1);
        gh2 = fmaf(hk, Wh[(64 + lane) * 33 + k], gh2);
    }
    float r  = 1.0f / (1.0f + __expf(-(gi0 + gh0)));
    float z  = 1.0f / (1.0f + __expf(-(gi1 + gh1)));
    float nn = tanhf(gi2 + r * gh2);
    float hnew = (1.0f - z) * nn + z * hv;

    if (finalStep) {
        if (bf) ((__nv_bfloat16*)outp)[n * 32 + lane] = __float2bfloat16(hnew);
        else    ((float*)outp)[n * 32 + lane] = hnew;
    } else {
        ((float*)outp)[n * 32 + lane] = hnew;        // g_h
    }
}

// ---------------------------------------------------------------------------
// Host: size-based binding (element counts) with positional fallback.
// ---------------------------------------------------------------------------
static int findBySz(const int* sizes, int n, long target, int occurrence) {
    int c = 0;
    for (int i = 0; i < n; i++)
        if ((long)sizes[i] == target) { if (c == occurrence) return i; c++; }
    return -1;
}

extern "C" void kernel_launch(void* const* d_in, const int* in_sizes, int n_in,
                              void* d_out, int out_size) {
    int i_nf = findBySz(in_sizes, n_in, (long)NN * ND, 0);
    int i_ei = findBySz(in_sizes, n_in, (long)2 * EE, 0);
    int i_ef = findBySz(in_sizes, n_in, (long)EE * ED, 0);
    int i_Wn = findBySz(in_sizes, n_in, (long)HD * ND, 0);
    int i_bn = findBySz(in_sizes, n_in, (long)HD, 0);
    int i_We = findBySz(in_sizes, n_in, (long)HD * HD * ED, 0);
    int i_be = findBySz(in_sizes, n_in, (long)HD * HD, 0);
    int i_g0 = findBySz(in_sizes, n_in, (long)3 * HD * HD, 0);
    int i_g1 = findBySz(in_sizes, n_in, (long)3 * HD * HD, 1);
    int i_q0 = findBySz(in_sizes, n_in, (long)3 * HD, 0);
    int i_q1 = findBySz(in_sizes, n_in, (long)3 * HD, 1);

    if (i_nf < 0 || i_ei < 0 || i_ef < 0 || i_Wn < 0 || i_bn < 0 ||
        i_We < 0 || i_be < 0 || i_g0 < 0 || i_g1 < 0 || i_q0 < 0 || i_q1 < 0) {
        i_nf = 0; i_ei = 1; i_ef = 2; i_Wn = 3; i_bn = 4;
        i_We = 5; i_be = 6; i_g0 = 7; i_g1 = 8; i_q0 = 9; i_q1 = 10;
    }

    const void* node_feat  = d_in[i_nf];
    const int*  edge_index = (const int*)d_in[i_ei];
    const void* edge_feat  = d_in[i_ef];
    const void* W_np       = d_in[i_Wn];
    const void* b_np       = d_in[i_bn];
    const void* W_e        = d_in[i_We];
    const void* b_e        = d_in[i_be];
    const void* W_ih       = d_in[i_g0];             // signature order: W_ih first
    const void* W_hh       = d_in[i_g1];
    const void* b_ih       = d_in[i_q0];
    const void* b_hh       = d_in[i_q1];

    const int* srcIdx = edge_index;                  // edge_index[0, :]
    const int* dstIdx = edge_index + EE;             // edge_index[1, :]

    static void* g_h_addr = nullptr;
    if (!g_h_addr) (void)cudaGetSymbolAddress(&g_h_addr, g_h);

    // Launch order arranged so msgKernel is the 4th launch (= the one ncu
    // empirically profiles): buildW2(0), nodeProj(1), compT(2), msg(3).
    buildW2Kernel<<<(TSL * HD + 255) / 256, 256>>>((const unsigned int*)node_feat, W_e, b_e);
    nodeProjKernel<<<NN / 8, 256>>>(node_feat, W_np, b_np);

    for (int step = 0; step < 3; step++) {
        compTKernel<<<296, 288>>>();
        msgKernel<<<EE / 32, 256>>>(srcIdx, dstIdx, edge_feat);
        int fin = (step == 2);
        void* hout = fin ? d_out : g_h_addr;
        gruKernel<<<NN / 8, 256>>>(W_ih, W_hh, b_ih, b_hh, hout, fin);
    }
}

// round 12
// speedup vs baseline: 1.5305x; 1.0235x over previous
#include <cuda_runtime.h>
#include <cuda_bf16.h>

// Problem constants (FIXED by reference): N=20000, E=160000, NODE_DIM=64, EDGE_DIM=16, H=32, STEPS=3
#define NN     20000
#define EE     160000
#define HD     32
#define ND     64
#define ED     16
#define TSL    544          // T row stride: 17 slices of 32 (16 edge-dims + bias)
#define NJT    68           // 544 / 8 n-tiles for the mma

// Scratch (allocation-free rule: __device__ globals)
__device__ int   g_flag;                     // 1 = float inputs are bf16, 0 = fp32
__device__ float g_h [NN * HD];              // node hidden state (fp32 internal)
__device__ float g_m [NN * HD];              // aggregated messages
__device__ float g_T [NN * TSL];             // per-node tensor (43.5 MB, L2-resident)
__device__ float g_B [NJT * 4 * 32 * 4];     // W2 tf32 frags: [jt][kk][lane]{b0h,b1h,b0l,b1l}

namespace {
struct EagerLoad {                            // materialize device globals at process start
    EagerLoad() { void* p = nullptr; (void)cudaGetSymbolAddress(&p, g_h); }
};
EagerLoad eager_load_;
}

// Dtype-agnostic float load (branch is warp-uniform on flag).
__device__ __forceinline__ float ldF(const void* p, long i, int bf) {
    return bf ? __bfloat162float(((const __nv_bfloat16*)p)[i])
              : ((const float*)p)[i];
}

__device__ __forceinline__ unsigned toTf32(float v) {
    unsigned r; asm("cvt.rna.tf32.f32 %0, %1;" : "=r"(r) : "f"(v)); return r;
}

#define MMA_TF32(d0,d1,d2,d3,a0,a1,a2,a3,b0,b1)                         \
    asm volatile("mma.sync.aligned.m16n8k8.row.col.f32.tf32.tf32.f32 "   \
        "{%0,%1,%2,%3}, {%4,%5,%6,%7}, {%8,%9}, {%0,%1,%2,%3};"          \
        : "+f"(d0), "+f"(d1), "+f"(d2), "+f"(d3)                          \
        : "r"(a0), "r"(a1), "r"(a2), "r"(a3), "r"(b0), "r"(b1))

// ---------------------------------------------------------------------------
// Detect input dtype from node_feat bit patterns (see R4 notes). Launch 0 so
// compTKernel lands at the profiled launch index (3).
// ---------------------------------------------------------------------------
__global__ void detectKernel(const unsigned int* __restrict__ nf) {
    int lane = threadIdx.x;
    int cnt = 0;
    for (int i = lane; i < 1024; i += 32) {
        unsigned int e = (nf[i] >> 7) & 0xFF;
        cnt += (e >= 110 && e <= 140) ? 1 : 0;
    }
#pragma unroll
    for (int o = 16; o > 0; o >>= 1) cnt += __shfl_down_sync(0xffffffffu, cnt, o);
    if (lane == 0) g_flag = (cnt > 512) ? 1 : 0;
}

// ---------------------------------------------------------------------------
// Build W2 tf32 B-fragments in mma frag order (hi/lo 3xTF32 split).
// Logical W2[j][k]: j = d*32+h; d<16 -> W_e[(h*32+k)*16+d]; d==16 -> b_e[h*32+k].
// Frag slot i: q=i&3 (0=b0h,1=b1h,2=b0l,3=b1l), lane=(i>>2)&31, kk=(i>>7)&3, jt=i>>9.
// b0: B[k=kk*8+(lane&3)][n=jt*8+(lane>>2)]; b1: k += 4.
// ---------------------------------------------------------------------------
__global__ void buildBKernel(const void* __restrict__ We, const void* __restrict__ be) {
    int bf = g_flag;
    int i = blockIdx.x * 256 + threadIdx.x;          // grid exact: 136*256 == NJT*512
    int q    = i & 3;
    int lane = (i >> 2) & 31;
    int kk   = (i >> 7) & 3;
    int jt   = i >> 9;
    int j = jt * 8 + (lane >> 2);                    // 0..543
    int k = kk * 8 + (lane & 3) + ((q & 1) ? 4 : 0);
    int d = j >> 5, h = j & 31;
    float v = (d < 16) ? ldF(We, (h * 32 + k) * 16 + d, bf)
                       : ldF(be, h * 32 + k, bf);
    unsigned hi = toTf32(v);
    unsigned out;
    if (q >= 2) out = toTf32(v - __uint_as_float(hi));   // lo part
    else        out = hi;
    g_B[i] = __uint_as_float(out);
}

// ---------------------------------------------------------------------------
// h = node_feat @ W_np^T + b_np ; also zero g_m. Warp per node.
// ---------------------------------------------------------------------------
__global__ void nodeProjKernel(const void* __restrict__ nf, const void* __restrict__ W,
                               const void* __restrict__ b) {
    __shared__ float Ws[32 * 65];
    int bf = g_flag;
    int tid = threadIdx.x;
    for (int i = tid; i < 32 * 64; i += 256)
        Ws[(i >> 6) * 65 + (i & 63)] = ldF(W, i, bf);
    __syncthreads();

    g_m[blockIdx.x * 256 + tid] = 0.0f;              // exact cover: 2500*256 == N*H

    int n = blockIdx.x * 8 + (tid >> 5);
    int lane = tid & 31;

    float v0 = ldF(nf, n * 64 + lane, bf);
    float v1 = ldF(nf, n * 64 + 32 + lane, bf);
    float acc = ldF(b, lane, bf);
#pragma unroll
    for (int k = 0; k < 32; k++) {
        float a0 = __shfl_sync(0xffffffffu, v0, k);
        float a1 = __shfl_sync(0xffffffffu, v1, k);
        acc = fmaf(a0, Ws[lane * 65 + k], acc);
        acc = fmaf(a1, Ws[lane * 65 + 32 + k], acc);
    }
    g_h[n * 32 + lane] = acc;
}

// ---------------------------------------------------------------------------
// compT via tensor cores: T[n,j] = sum_k h[n,k] * W2[j,k]
// mma.m16n8k8 tf32 with 3xTF32 split (fp32-equivalent precision).
// Block = 128 thr (4 warps x m16 node-tiles = 64 nodes); 313 blocks.
// A (h) staged in smem pad-36 (conflict-free: bank = l + 4t); B frags one
// LDG.128/lane per (jt,kk); jt unrolled x2 for mma-latency ILP.
// ---------------------------------------------------------------------------
__global__ void __launch_bounds__(128) compTKernel() {
    __shared__ float hs[64][36];
    int tid = threadIdx.x, w = tid >> 5, l = tid & 31;
    int n0 = blockIdx.x * 64;

    for (int i = tid; i < 64 * 32; i += 128) {
        int r = i >> 5, c = i & 31;
        int n = n0 + r;
        hs[r][c] = (n < NN) ? g_h[n * 32 + c] : 0.0f;
    }
    __syncthreads();

    int r0 = w * 16 + (l >> 2);
    int c0 = l & 3;
    unsigned ah[16], al[16];
#pragma unroll
    for (int kk = 0; kk < 4; kk++) {
#pragma unroll
        for (int p = 0; p < 4; p++) {
            int rr = r0 + ((p & 1) ? 8 : 0);
            int cc = kk * 8 + c0 + ((p & 2) ? 4 : 0);
            float v = hs[rr][cc];
            unsigned hi = toTf32(v);
            ah[kk * 4 + p] = hi;
            al[kk * 4 + p] = toTf32(v - __uint_as_float(hi));
        }
    }

    int nr0 = n0 + w * 16 + (l >> 2);
    int nr1 = nr0 + 8;
    const float4* Bp = reinterpret_cast<const float4*>(g_B) + l;

    for (int jt = 0; jt < NJT; jt += 2) {
        float d0 = 0, d1 = 0, d2 = 0, d3 = 0;        // tile jt
        float e0 = 0, e1 = 0, e2 = 0, e3 = 0;        // tile jt+1
#pragma unroll
        for (int kk = 0; kk < 4; kk++) {
            float4 ba = Bp[(jt * 4 + kk) * 32];
            float4 bb = Bp[((jt + 1) * 4 + kk) * 32];
            unsigned a0 = ah[kk*4], a1 = ah[kk*4+1], a2 = ah[kk*4+2], a3 = ah[kk*4+3];
            unsigned l0 = al[kk*4], l1 = al[kk*4+1], l2 = al[kk*4+2], l3 = al[kk*4+3];
            unsigned b0h = __float_as_uint(ba.x), b1h = __float_as_uint(ba.y);
            unsigned b0l = __float_as_uint(ba.z), b1l = __float_as_uint(ba.w);
            unsigned c0h = __float_as_uint(bb.x), c1h = __float_as_uint(bb.y);
            unsigned c0l = __float_as_uint(bb.z), c1l = __float_as_uint(bb.w);
            MMA_TF32(d0,d1,d2,d3, a0,a1,a2,a3, b0h,b1h);
            MMA_TF32(e0,e1,e2,e3, a0,a1,a2,a3, c0h,c1h);
            MMA_TF32(d0,d1,d2,d3, a0,a1,a2,a3, b0l,b1l);
            MMA_TF32(e0,e1,e2,e3, a0,a1,a2,a3, c0l,c1l);
            MMA_TF32(d0,d1,d2,d3, l0,l1,l2,l3, b0h,b1h);
            MMA_TF32(e0,e1,e2,e3, l0,l1,l2,l3, c0h,c1h);
        }
        int jb = jt * 8 + 2 * (l & 3);
        if (nr0 < NN) {
            *reinterpret_cast<float2*>(&g_T[(size_t)nr0 * TSL + jb])     = make_float2(d0, d1);
            *reinterpret_cast<float2*>(&g_T[(size_t)nr0 * TSL + jb + 8]) = make_float2(e0, e1);
        }
        if (nr1 < NN) {
            *reinterpret_cast<float2*>(&g_T[(size_t)nr1 * TSL + jb])     = make_float2(d2, d3);
            *reinterpret_cast<float2*>(&g_T[(size_t)nr1 * TSL + jb + 8]) = make_float2(e2, e3);
        }
    }
}

// ---------------------------------------------------------------------------
// msg: 4 edges per warp, 8 lanes per edge, each lane owns a 4-channel quad.
// T loads float4 (128B/row coalesced); scatter via red.global.add.v4.f32.
// (Frozen from R11: 25.2us, at its L2 gather bound.)
// ---------------------------------------------------------------------------
__global__ void msgKernel(const int* __restrict__ src, const int* __restrict__ dst,
                          const void* __restrict__ ef) {
    int bf = g_flag;
    int lane = threadIdx.x & 31;
    int g    = lane >> 3;                            // edge slot within warp (0..3)
    int sub  = lane & 7;                             // channel quad (0..7)
    int e = (blockIdx.x * (256 / 32) + (threadIdx.x >> 5)) * 4 + g;   // e < EE exact

    int s = src[e]; if ((unsigned)s >= (unsigned)NN) s = 0;
    int d = dst[e]; if ((unsigned)d >= (unsigned)NN) d = 0;

    float f0 = ldF(ef, (long)e * 16 + sub * 2,     bf);
    float f1 = ldF(ef, (long)e * 16 + sub * 2 + 1, bf);

    const float* Trow = g_T + (size_t)s * TSL;
    float4 t4[17];
#pragma unroll
    for (int dd = 0; dd < 16; dd++)
        t4[dd] = *reinterpret_cast<const float4*>(Trow + dd * 32 + sub * 4);
    t4[16] = *reinterpret_cast<const float4*>(Trow + 512 + sub * 4);   // bias quad

    float4 acc = t4[16];
#pragma unroll
    for (int dd = 0; dd < 16; dd++) {
        int sl = g * 8 + (dd >> 1);
        float c = __shfl_sync(0xffffffffu, (dd & 1) ? f1 : f0, sl);
        acc.x = fmaf(c, t4[dd].x, acc.x);
        acc.y = fmaf(c, t4[dd].y, acc.y);
        acc.z = fmaf(c, t4[dd].z, acc.z);
        acc.w = fmaf(c, t4[dd].w, acc.w);
    }

    float* outp = &g_m[d * 32 + sub * 4];            // 16B-aligned
    asm volatile("red.global.add.v4.f32 [%0], {%1, %2, %3, %4};"
                 :: "l"(outp), "f"(acc.x), "f"(acc.y), "f"(acc.z), "f"(acc.w)
                 : "memory");
}

// ---------------------------------------------------------------------------
// GRUCell (torch layout r,z,n). Warp per node; 6 independent FMA chains.
// Final step writes d_out in detected dtype. Re-zeroes g_m for replay.
// ---------------------------------------------------------------------------
__global__ void gruKernel(const void* __restrict__ W_ih, const void* __restrict__ W_hh,
                          const void* __restrict__ b_ih, const void* __restrict__ b_hh,
                          void* __restrict__ outp, int finalStep) {
    __shared__ float Wi[96 * 33];
    __shared__ float Wh[96 * 33];
    int bf = g_flag;
    int tid = threadIdx.x;
    for (int i = tid; i < 96 * 32; i += 256) {
        int j = i >> 5, k = i & 31;
        Wi[j * 33 + k] = ldF(W_ih, i, bf);
        Wh[j * 33 + k] = ldF(W_hh, i, bf);
    }
    __syncthreads();

    int n = blockIdx.x * 8 + (tid >> 5);             // grid exact: n < NN
    int lane = tid & 31;

    float mv = g_m[n * 32 + lane];
    float hv = g_h[n * 32 + lane];
    g_m[n * 32 + lane] = 0.0f;                       // reset for next step / replay

    float gi0 = ldF(b_ih, lane, bf), gi1 = ldF(b_ih, 32 + lane, bf), gi2 = ldF(b_ih, 64 + lane, bf);
    float gh0 = ldF(b_hh, lane, bf), gh1 = ldF(b_hh, 32 + lane, bf), gh2 = ldF(b_hh, 64 + lane, bf);
#pragma unroll
    for (int k = 0; k < 32; k++) {
        float mk = __shfl_sync(0xffffffffu, mv, k);
        float hk = __shfl_sync(0xffffffffu, hv, k);
        gi0 = fmaf(mk, Wi[lane * 33 + k],        gi0);
        gi1 = fmaf(mk, Wi[(32 + lane) * 33 + k], gi1);
        gi2 = fmaf(mk, Wi[(64 + lane) * 33 + k], gi2);
        gh0 = fmaf(hk, Wh[lane * 33 + k],        gh0);
        gh1 = fmaf(hk, Wh[(32 + lane) * 33 + k], gh1);
        gh2 = fmaf(hk, Wh[(64 + lane) * 33 + k], gh2);
    }
    float r  = 1.0f / (1.0f + __expf(-(gi0 + gh0)));
    float z  = 1.0f / (1.0f + __expf(-(gi1 + gh1)));
    float nn = tanhf(gi2 + r * gh2);
    float hnew = (1.0f - z) * nn + z * hv;

    if (finalStep) {
        if (bf) ((__nv_bfloat16*)outp)[n * 32 + lane] = __float2bfloat16(hnew);
        else    ((float*)outp)[n * 32 + lane] = hnew;
    } else {
        ((float*)outp)[n * 32 + lane] = hnew;        // g_h
    }
}

// ---------------------------------------------------------------------------
// Host: size-based binding (element counts) with positional fallback.
// ---------------------------------------------------------------------------
static int findBySz(const int* sizes, int n, long target, int occurrence) {
    int c = 0;
    for (int i = 0; i < n; i++)
        if ((long)sizes[i] == target) { if (c == occurrence) return i; c++; }
    return -1;
}

extern "C" void kernel_launch(void* const* d_in, const int* in_sizes, int n_in,
                              void* d_out, int out_size) {
    int i_nf = findBySz(in_sizes, n_in, (long)NN * ND, 0);
    int i_ei = findBySz(in_sizes, n_in, (long)2 * EE, 0);
    int i_ef = findBySz(in_sizes, n_in, (long)EE * ED, 0);
    int i_Wn = findBySz(in_sizes, n_in, (long)HD * ND, 0);
    int i_bn = findBySz(in_sizes, n_in, (long)HD, 0);
    int i_We = findBySz(in_sizes, n_in, (long)HD * HD * ED, 0);
    int i_be = findBySz(in_sizes, n_in, (long)HD * HD, 0);
    int i_g0 = findBySz(in_sizes, n_in, (long)3 * HD * HD, 0);
    int i_g1 = findBySz(in_sizes, n_in, (long)3 * HD * HD, 1);
    int i_q0 = findBySz(in_sizes, n_in, (long)3 * HD, 0);
    int i_q1 = findBySz(in_sizes, n_in, (long)3 * HD, 1);

    if (i_nf < 0 || i_ei < 0 || i_ef < 0 || i_Wn < 0 || i_bn < 0 ||
        i_We < 0 || i_be < 0 || i_g0 < 0 || i_g1 < 0 || i_q0 < 0 || i_q1 < 0) {
        i_nf = 0; i_ei = 1; i_ef = 2; i_Wn = 3; i_bn = 4;
        i_We = 5; i_be = 6; i_g0 = 7; i_g1 = 8; i_q0 = 9; i_q1 = 10;
    }

    const void* node_feat  = d_in[i_nf];
    const int*  edge_index = (const int*)d_in[i_ei];
    const void* edge_feat  = d_in[i_ef];
    const void* W_np       = d_in[i_Wn];
    const void* b_np       = d_in[i_bn];
    const void* W_e        = d_in[i_We];
    const void* b_e        = d_in[i_be];
    const void* W_ih       = d_in[i_g0];             // signature order: W_ih first
    const void* W_hh       = d_in[i_g1];
    const void* b_ih       = d_in[i_q0];
    const void* b_hh       = d_in[i_q1];

    const int* srcIdx = edge_index;                  // edge_index[0, :]
    const int* dstIdx = edge_index + EE;             // edge_index[1, :]

    static void* g_h_addr = nullptr;
    if (!g_h_addr) (void)cudaGetSymbolAddress(&g_h_addr, g_h);

    // Launch order: detect(0), buildB(1), nodeProj(2), compT(3 = profiled), msg(4)...
    detectKernel<<<1, 32>>>((const unsigned int*)node_feat);
    buildBKernel<<<136, 256>>>(W_e, b_e);            // 136*256 == NJT*512 exact
    nodeProjKernel<<<NN / 8, 256>>>(node_feat, W_np, b_np);

    for (int step = 0; step < 3; step++) {
        compTKernel<<<(NN + 63) / 64, 128>>>();
        msgKernel<<<EE / 32, 256>>>(srcIdx, dstIdx, edge_feat);
        int fin = (step == 2);
        void* hout = fin ? d_out : g_h_addr;
        gruKernel<<<NN / 8, 256>>>(W_ih, W_hh, b_ih, b_hh, hout, fin);
    }
}

// round 13
// speedup vs baseline: 1.6716x; 1.0922x over previous
#include <cuda_runtime.h>
#include <cuda_bf16.h>

// Problem constants (FIXED by reference): N=20000, E=160000, NODE_DIM=64, EDGE_DIM=16, H=32, STEPS=3
#define NN     20000
#define EE     160000
#define HD     32
#define ND     64
#define ED     16
#define TSL    544          // T row stride: 17 slices of 32 (16 edge-dims + bias)
#define NJT    68           // 544 / 8 n-tiles for the mma
#define JHALF  34           // jt tiles per block (j-split = 2)

// Scratch (allocation-free rule: __device__ globals)
__device__ int   g_flag;                     // 1 = float inputs are bf16, 0 = fp32
__device__ float g_h [NN * HD];              // node hidden state (fp32 internal)
__device__ float g_m [NN * HD];              // aggregated messages
__device__ float g_T [NN * TSL];             // per-node tensor (43.5 MB, L2-resident)
__device__ float g_B [NJT * 4 * 32 * 4];     // W2 tf32 frags: [jt][kk][lane]{b0h,b1h,b0l,b1l}

namespace {
struct EagerLoad {                            // materialize device globals at process start
    EagerLoad() { void* p = nullptr; (void)cudaGetSymbolAddress(&p, g_h); }
};
EagerLoad eager_load_;
}

// Dtype-agnostic float load (branch is warp-uniform on flag).
__device__ __forceinline__ float ldF(const void* p, long i, int bf) {
    return bf ? __bfloat162float(((const __nv_bfloat16*)p)[i])
              : ((const float*)p)[i];
}

__device__ __forceinline__ unsigned toTf32(float v) {
    unsigned r; asm("cvt.rna.tf32.f32 %0, %1;" : "=r"(r) : "f"(v)); return r;
}

#define MMA_TF32(d0,d1,d2,d3,a0,a1,a2,a3,b0,b1)                         \
    asm volatile("mma.sync.aligned.m16n8k8.row.col.f32.tf32.tf32.f32 "   \
        "{%0,%1,%2,%3}, {%4,%5,%6,%7}, {%8,%9}, {%0,%1,%2,%3};"          \
        : "+f"(d0), "+f"(d1), "+f"(d2), "+f"(d3)                          \
        : "r"(a0), "r"(a1), "r"(a2), "r"(a3), "r"(b0), "r"(b1))

// ---------------------------------------------------------------------------
// Detect input dtype from node_feat bit patterns (see R4 notes).
// ---------------------------------------------------------------------------
__global__ void detectKernel(const unsigned int* __restrict__ nf) {
    int lane = threadIdx.x;
    int cnt = 0;
    for (int i = lane; i < 1024; i += 32) {
        unsigned int e = (nf[i] >> 7) & 0xFF;
        cnt += (e >= 110 && e <= 140) ? 1 : 0;
    }
#pragma unroll
    for (int o = 16; o > 0; o >>= 1) cnt += __shfl_down_sync(0xffffffffu, cnt, o);
    if (lane == 0) g_flag = (cnt > 512) ? 1 : 0;
}

// ---------------------------------------------------------------------------
// Build W2 tf32 B-fragments in mma frag order (hi/lo 3xTF32 split).
// Logical W2[j][k]: j = d*32+h; d<16 -> W_e[(h*32+k)*16+d]; d==16 -> b_e[h*32+k].
// Frag slot i: q=i&3 (0=b0h,1=b1h,2=b0l,3=b1l), lane=(i>>2)&31, kk=(i>>7)&3, jt=i>>9.
// ---------------------------------------------------------------------------
__global__ void buildBKernel(const void* __restrict__ We, const void* __restrict__ be) {
    int bf = g_flag;
    int i = blockIdx.x * 256 + threadIdx.x;          // grid exact: 136*256 == NJT*512
    int q    = i & 3;
    int lane = (i >> 2) & 31;
    int kk   = (i >> 7) & 3;
    int jt   = i >> 9;
    int j = jt * 8 + (lane >> 2);                    // 0..543
    int k = kk * 8 + (lane & 3) + ((q & 1) ? 4 : 0);
    int d = j >> 5, h = j & 31;
    float v = (d < 16) ? ldF(We, (h * 32 + k) * 16 + d, bf)
                       : ldF(be, h * 32 + k, bf);
    unsigned hi = toTf32(v);
    unsigned out;
    if (q >= 2) out = toTf32(v - __uint_as_float(hi));   // lo part
    else        out = hi;
    g_B[i] = __uint_as_float(out);
}

// ---------------------------------------------------------------------------
// h = node_feat @ W_np^T + b_np ; also zero g_m. Warp per node.
// ---------------------------------------------------------------------------
__global__ void nodeProjKernel(const void* __restrict__ nf, const void* __restrict__ W,
                               const void* __restrict__ b) {
    __shared__ float Ws[32 * 65];
    int bf = g_flag;
    int tid = threadIdx.x;
    for (int i = tid; i < 32 * 64; i += 256)
        Ws[(i >> 6) * 65 + (i & 63)] = ldF(W, i, bf);
    __syncthreads();

    g_m[blockIdx.x * 256 + tid] = 0.0f;              // exact cover: 2500*256 == N*H

    int n = blockIdx.x * 8 + (tid >> 5);
    int lane = tid & 31;

    float v0 = ldF(nf, n * 64 + lane, bf);
    float v1 = ldF(nf, n * 64 + 32 + lane, bf);
    float acc = ldF(b, lane, bf);
#pragma unroll
    for (int k = 0; k < 32; k++) {
        float a0 = __shfl_sync(0xffffffffu, v0, k);
        float a1 = __shfl_sync(0xffffffffu, v1, k);
        acc = fmaf(a0, Ws[lane * 65 + k], acc);
        acc = fmaf(a1, Ws[lane * 65 + 32 + k], acc);
    }
    g_h[n * 32 + lane] = acc;
}

// ---------------------------------------------------------------------------
// compT via tensor cores: T[n,j] = sum_k h[n,k] * W2[j,k]
// mma.m16n8k8 tf32, 3xTF32 split. j-SPLIT x2: block = (node-tile, j-half),
// grid 626 -> ~4 blocks/SM (R12 ran 313 blocks -> 2/SM, occ 12.8%, fully
// latency-bound). B double-buffered in registers (prefetch 1 pair ahead).
// ---------------------------------------------------------------------------
__global__ void __launch_bounds__(128) compTKernel() {
    __shared__ float hs[64][36];
    int tid = threadIdx.x, w = tid >> 5, l = tid & 31;
    int nb = blockIdx.x >> 1;                        // node tile (0..312)
    int jh = blockIdx.x & 1;                         // j half
    int n0 = nb * 64;

    for (int i = tid; i < 64 * 32; i += 128) {
        int r = i >> 5, c = i & 31;
        int n = n0 + r;
        hs[r][c] = (n < NN) ? g_h[n * 32 + c] : 0.0f;
    }
    __syncthreads();

    int r0 = w * 16 + (l >> 2);
    int c0 = l & 3;
    unsigned ah[16], al[16];
#pragma unroll
    for (int kk = 0; kk < 4; kk++) {
#pragma unroll
        for (int p = 0; p < 4; p++) {
            int rr = r0 + ((p & 1) ? 8 : 0);
            int cc = kk * 8 + c0 + ((p & 2) ? 4 : 0);
            float v = hs[rr][cc];
            unsigned hi = toTf32(v);
            ah[kk * 4 + p] = hi;
            al[kk * 4 + p] = toTf32(v - __uint_as_float(hi));
        }
    }

    int nr0 = n0 + w * 16 + (l >> 2);
    int nr1 = nr0 + 8;
    const float4* Bp = reinterpret_cast<const float4*>(g_B) + l;
    int jt0 = jh * JHALF;

    float4 cur[8];
#pragma unroll
    for (int kk = 0; kk < 4; kk++) {
        cur[kk]     = Bp[(jt0 * 4 + kk) * 32];
        cur[4 + kk] = Bp[((jt0 + 1) * 4 + kk) * 32];
    }

    for (int jt = jt0; jt < jt0 + JHALF; jt += 2) {
        float4 nxt[8];
        if (jt + 2 < jt0 + JHALF) {
#pragma unroll
            for (int kk = 0; kk < 4; kk++) {
                nxt[kk]     = Bp[((jt + 2) * 4 + kk) * 32];
                nxt[4 + kk] = Bp[((jt + 3) * 4 + kk) * 32];
            }
        }
        float d0 = 0, d1 = 0, d2 = 0, d3 = 0;        // tile jt
        float e0 = 0, e1 = 0, e2 = 0, e3 = 0;        // tile jt+1
#pragma unroll
        for (int kk = 0; kk < 4; kk++) {
            float4 ba = cur[kk], bb = cur[4 + kk];
            unsigned a0 = ah[kk*4], a1 = ah[kk*4+1], a2 = ah[kk*4+2], a3 = ah[kk*4+3];
            unsigned l0 = al[kk*4], l1 = al[kk*4+1], l2 = al[kk*4+2], l3 = al[kk*4+3];
            unsigned b0h = __float_as_uint(ba.x), b1h = __float_as_uint(ba.y);
            unsigned b0l = __float_as_uint(ba.z), b1l = __float_as_uint(ba.w);
            unsigned c0h = __float_as_uint(bb.x), c1h = __float_as_uint(bb.y);
            unsigned c0l = __float_as_uint(bb.z), c1l = __float_as_uint(bb.w);
            MMA_TF32(d0,d1,d2,d3, a0,a1,a2,a3, b0h,b1h);
            MMA_TF32(e0,e1,e2,e3, a0,a1,a2,a3, c0h,c1h);
            MMA_TF32(d0,d1,d2,d3, a0,a1,a2,a3, b0l,b1l);
            MMA_TF32(e0,e1,e2,e3, a0,a1,a2,a3, c0l,c1l);
            MMA_TF32(d0,d1,d2,d3, l0,l1,l2,l3, b0h,b1h);
            MMA_TF32(e0,e1,e2,e3, l0,l1,l2,l3, c0h,c1h);
        }
#pragma unroll
        for (int x = 0; x < 8; x++) cur[x] = nxt[x];

        int jb = jt * 8 + 2 * (l & 3);
        if (nr0 < NN) {
            *reinterpret_cast<float2*>(&g_T[(size_t)nr0 * TSL + jb])     = make_float2(d0, d1);
            *reinterpret_cast<float2*>(&g_T[(size_t)nr0 * TSL + jb + 8]) = make_float2(e0, e1);
        }
        if (nr1 < NN) {
            *reinterpret_cast<float2*>(&g_T[(size_t)nr1 * TSL + jb])     = make_float2(d2, d3);
            *reinterpret_cast<float2*>(&g_T[(size_t)nr1 * TSL + jb + 8]) = make_float2(e2, e3);
        }
    }
}

// ---------------------------------------------------------------------------
// msg: 4 edges per warp, 8 lanes per edge, each lane owns a 4-channel quad.
// T loads float4 (128B/row coalesced); scatter via red.global.add.v4.f32.
// (Frozen from R11: ~25us, at its L2 gather bound.)
// ---------------------------------------------------------------------------
__global__ void msgKernel(const int* __restrict__ src, const int* __restrict__ dst,
                          const void* __restrict__ ef) {
    int bf = g_flag;
    int lane = threadIdx.x & 31;
    int g    = lane >> 3;                            // edge slot within warp (0..3)
    int sub  = lane & 7;                             // channel quad (0..7)
    int e = (blockIdx.x * (256 / 32) + (threadIdx.x >> 5)) * 4 + g;   // e < EE exact

    int s = src[e]; if ((unsigned)s >= (unsigned)NN) s = 0;
    int d = dst[e]; if ((unsigned)d >= (unsigned)NN) d = 0;

    float f0 = ldF(ef, (long)e * 16 + sub * 2,     bf);
    float f1 = ldF(ef, (long)e * 16 + sub * 2 + 1, bf);

    const float* Trow = g_T + (size_t)s * TSL;
    float4 t4[17];
#pragma unroll
    for (int dd = 0; dd < 16; dd++)
        t4[dd] = *reinterpret_cast<const float4*>(Trow + dd * 32 + sub * 4);
    t4[16] = *reinterpret_cast<const float4*>(Trow + 512 + sub * 4);   // bias quad

    float4 acc = t4[16];
#pragma unroll
    for (int dd = 0; dd < 16; dd++) {
        int sl = g * 8 + (dd >> 1);
        float c = __shfl_sync(0xffffffffu, (dd & 1) ? f1 : f0, sl);
        acc.x = fmaf(c, t4[dd].x, acc.x);
        acc.y = fmaf(c, t4[dd].y, acc.y);
        acc.z = fmaf(c, t4[dd].z, acc.z);
        acc.w = fmaf(c, t4[dd].w, acc.w);
    }

    float* outp = &g_m[d * 32 + sub * 4];            // 16B-aligned
    asm volatile("red.global.add.v4.f32 [%0], {%1, %2, %3, %4};"
                 :: "l"(outp), "f"(acc.x), "f"(acc.y), "f"(acc.z), "f"(acc.w)
                 : "memory");
}

// ---------------------------------------------------------------------------
// GRUCell (torch layout r,z,n). Warp per node; 6 independent FMA chains.
// Final step writes d_out in detected dtype. Re-zeroes g_m for replay.
// ---------------------------------------------------------------------------
__global__ void gruKernel(const void* __restrict__ W_ih, const void* __restrict__ W_hh,
                          const void* __restrict__ b_ih, const void* __restrict__ b_hh,
                          void* __restrict__ outp, int finalStep) {
    __shared__ float Wi[96 * 33];
    __shared__ float Wh[96 * 33];
    int bf = g_flag;
    int tid = threadIdx.x;
    for (int i = tid; i < 96 * 32; i += 256) {
        int j = i >> 5, k = i & 31;
        Wi[j * 33 + k] = ldF(W_ih, i, bf);
        Wh[j * 33 + k] = ldF(W_hh, i, bf);
    }
    __syncthreads();

    int n = blockIdx.x * 8 + (tid >> 5);             // grid exact: n < NN
    int lane = tid & 31;

    float mv = g_m[n * 32 + lane];
    float hv = g_h[n * 32 + lane];
    g_m[n * 32 + lane] = 0.0f;                       // reset for next step / replay

    float gi0 = ldF(b_ih, lane, bf), gi1 = ldF(b_ih, 32 + lane, bf), gi2 = ldF(b_ih, 64 + lane, bf);
    float gh0 = ldF(b_hh, lane, bf), gh1 = ldF(b_hh, 32 + lane, bf), gh2 = ldF(b_hh, 64 + lane, bf);
#pragma unroll
    for (int k = 0; k < 32; k++) {
        float mk = __shfl_sync(0xffffffffu, mv, k);
        float hk = __shfl_sync(0xffffffffu, hv, k);
        gi0 = fmaf(mk, Wi[lane * 33 + k],        gi0);
        gi1 = fmaf(mk, Wi[(32 + lane) * 33 + k], gi1);
        gi2 = fmaf(mk, Wi[(64 + lane) * 33 + k], gi2);
        gh0 = fmaf(hk, Wh[lane * 33 + k],        gh0);
        gh1 = fmaf(hk, Wh[(32 + lane) * 33 + k], gh1);
        gh2 = fmaf(hk, Wh[(64 + lane) * 33 + k], gh2);
    }
    float r  = 1.0f / (1.0f + __expf(-(gi0 + gh0)));
    float z  = 1.0f / (1.0f + __expf(-(gi1 + gh1)));
    float nn = tanhf(gi2 + r * gh2);
    float hnew = (1.0f - z) * nn + z * hv;

    if (finalStep) {
        if (bf) ((__nv_bfloat16*)outp)[n * 32 + lane] = __float2bfloat16(hnew);
        else    ((float*)outp)[n * 32 + lane] = hnew;
    } else {
        ((float*)outp)[n * 32 + lane] = hnew;        // g_h
    }
}

// ---------------------------------------------------------------------------
// Host: size-based binding (element counts) with positional fallback.
// ---------------------------------------------------------------------------
static int findBySz(const int* sizes, int n, long target, int occurrence) {
    int c = 0;
    for (int i = 0; i < n; i++)
        if ((long)sizes[i] == target) { if (c == occurrence) return i; c++; }
    return -1;
}

extern "C" void kernel_launch(void* const* d_in, const int* in_sizes, int n_in,
                              void* d_out, int out_size) {
    int i_nf = findBySz(in_sizes, n_in, (long)NN * ND, 0);
    int i_ei = findBySz(in_sizes, n_in, (long)2 * EE, 0);
    int i_ef = findBySz(in_sizes, n_in, (long)EE * ED, 0);
    int i_Wn = findBySz(in_sizes, n_in, (long)HD * ND, 0);
    int i_bn = findBySz(in_sizes, n_in, (long)HD, 0);
    int i_We = findBySz(in_sizes, n_in, (long)HD * HD * ED, 0);
    int i_be = findBySz(in_sizes, n_in, (long)HD * HD, 0);
    int i_g0 = findBySz(in_sizes, n_in, (long)3 * HD * HD, 0);
    int i_g1 = findBySz(in_sizes, n_in, (long)3 * HD * HD, 1);
    int i_q0 = findBySz(in_sizes, n_in, (long)3 * HD, 0);
    int i_q1 = findBySz(in_sizes, n_in, (long)3 * HD, 1);

    if (i_nf < 0 || i_ei < 0 || i_ef < 0 || i_Wn < 0 || i_bn < 0 ||
        i_We < 0 || i_be < 0 || i_g0 < 0 || i_g1 < 0 || i_q0 < 0 || i_q1 < 0) {
        i_nf = 0; i_ei = 1; i_ef = 2; i_Wn = 3; i_bn = 4;
        i_We = 5; i_be = 6; i_g0 = 7; i_g1 = 8; i_q0 = 9; i_q1 = 10;
    }

    const void* node_feat  = d_in[i_nf];
    const int*  edge_index = (const int*)d_in[i_ei];
    const void* edge_feat  = d_in[i_ef];
    const void* W_np       = d_in[i_Wn];
    const void* b_np       = d_in[i_bn];
    const void* W_e        = d_in[i_We];
    const void* b_e        = d_in[i_be];
    const void* W_ih       = d_in[i_g0];             // signature order: W_ih first
    const void* W_hh       = d_in[i_g1];
    const void* b_ih       = d_in[i_q0];
    const void* b_hh       = d_in[i_q1];

    const int* srcIdx = edge_index;                  // edge_index[0, :]
    const int* dstIdx = edge_index + EE;             // edge_index[1, :]

    static void* g_h_addr = nullptr;
    if (!g_h_addr) (void)cudaGetSymbolAddress(&g_h_addr, g_h);

    // Launch order: detect(0), buildB(1), nodeProj(2), compT(3 = profiled), msg(4)...
    detectKernel<<<1, 32>>>((const unsigned int*)node_feat);
    buildBKernel<<<136, 256>>>(W_e, b_e);            // 136*256 == NJT*512 exact
    nodeProjKernel<<<NN / 8, 256>>>(node_feat, W_np, b_np);

    for (int step = 0; step < 3; step++) {
        compTKernel<<<((NN + 63) / 64) * 2, 128>>>();
        msgKernel<<<EE / 32, 256>>>(srcIdx, dstIdx, edge_feat);
        int fin = (step == 2);
        void* hout = fin ? d_out : g_h_addr;
        gruKernel<<<NN / 8, 256>>>(W_ih, W_hh, b_ih, b_hh, hout, fin);
    }
}

// round 15
// speedup vs baseline: 1.7965x; 1.0747x over previous
#include <cuda_runtime.h>
#include <cuda_bf16.h>

// Problem constants (FIXED by reference): N=20000, E=160000, NODE_DIM=64, EDGE_DIM=16, H=32, STEPS=3
#define NN     20000
#define EE     160000
#define HD     32
#define ND     64
#define ED     16
#define TSL    544          // T row stride: 17 slices of 32 (16 edge-dims + bias)
#define NJT    68           // 544 / 8 n-tiles for the mma
#define JHALF  34           // jt tiles per block (j-split = 2)

// Scratch (allocation-free rule: __device__ globals)
__device__ int   g_flag;                     // 1 = float inputs are bf16, 0 = fp32
__device__ float g_h [NN * HD];              // node hidden state (fp32 internal)
__device__ float g_m [NN * HD];              // aggregated messages
__device__ float g_T [NN * TSL];             // per-node tensor (43.5 MB, L2-resident)
__device__ float g_B [NJT * 4 * 32 * 4];     // W2 tf32 frags: [jt][kk][lane]{b0h,b1h,b0l,b1l}

namespace {
struct EagerLoad {                            // materialize device globals at process start
    EagerLoad() { void* p = nullptr; (void)cudaGetSymbolAddress(&p, g_h); }
};
EagerLoad eager_load_;
}

// Dtype-agnostic float load (branch is warp-uniform on flag).
__device__ __forceinline__ float ldF(const void* p, long i, int bf) {
    return bf ? __bfloat162float(((const __nv_bfloat16*)p)[i])
              : ((const float*)p)[i];
}

__device__ __forceinline__ unsigned toTf32(float v) {
    unsigned r; asm("cvt.rna.tf32.f32 %0, %1;" : "=r"(r) : "f"(v)); return r;
}

#define MMA_TF32(d0,d1,d2,d3,a0,a1,a2,a3,b0,b1)                         \
    asm volatile("mma.sync.aligned.m16n8k8.row.col.f32.tf32.tf32.f32 "   \
        "{%0,%1,%2,%3}, {%4,%5,%6,%7}, {%8,%9}, {%0,%1,%2,%3};"          \
        : "+f"(d0), "+f"(d1), "+f"(d2), "+f"(d3)                          \
        : "r"(a0), "r"(a1), "r"(a2), "r"(a3), "r"(b0), "r"(b1))

// ---------------------------------------------------------------------------
// Detect input dtype from node_feat bit patterns (see R4 notes).
// ---------------------------------------------------------------------------
__global__ void detectKernel(const unsigned int* __restrict__ nf) {
    int lane = threadIdx.x;
    int cnt = 0;
    for (int i = lane; i < 1024; i += 32) {
        unsigned int e = (nf[i] >> 7) & 0xFF;
        cnt += (e >= 110 && e <= 140) ? 1 : 0;
    }
#pragma unroll
    for (int o = 16; o > 0; o >>= 1) cnt += __shfl_down_sync(0xffffffffu, cnt, o);
    if (lane == 0) g_flag = (cnt > 512) ? 1 : 0;
}

// ---------------------------------------------------------------------------
// Build W2 tf32 B-fragments in mma frag order (hi/lo 3-term split — R14
// proved the lo parts are NOT negligible; this is R13's proven version).
// Logical W2[j][k]: j = d*32+h; d<16 -> W_e[(h*32+k)*16+d]; d==16 -> b_e[h*32+k].
// Frag slot i: q=i&3 (0=b0h,1=b1h,2=b0l,3=b1l), lane=(i>>2)&31, kk=(i>>7)&3, jt=i>>9.
// ---------------------------------------------------------------------------
__global__ void buildBKernel(const void* __restrict__ We, const void* __restrict__ be) {
    int bf = g_flag;
    int i = blockIdx.x * 256 + threadIdx.x;          // grid exact: 136*256 == NJT*512
    int q    = i & 3;
    int lane = (i >> 2) & 31;
    int kk   = (i >> 7) & 3;
    int jt   = i >> 9;
    int j = jt * 8 + (lane >> 2);                    // 0..543
    int k = kk * 8 + (lane & 3) + ((q & 1) ? 4 : 0);
    int d = j >> 5, h = j & 31;
    float v = (d < 16) ? ldF(We, (h * 32 + k) * 16 + d, bf)
                       : ldF(be, h * 32 + k, bf);
    unsigned hi = toTf32(v);
    unsigned out;
    if (q >= 2) out = toTf32(v - __uint_as_float(hi));   // lo part
    else        out = hi;
    g_B[i] = __uint_as_float(out);
}

// ---------------------------------------------------------------------------
// h = node_feat @ W_np^T + b_np ; also zero g_m. Warp per node.
// ---------------------------------------------------------------------------
__global__ void nodeProjKernel(const void* __restrict__ nf, const void* __restrict__ W,
                               const void* __restrict__ b) {
    __shared__ float Ws[32 * 65];
    int bf = g_flag;
    int tid = threadIdx.x;
    for (int i = tid; i < 32 * 64; i += 256)
        Ws[(i >> 6) * 65 + (i & 63)] = ldF(W, i, bf);
    __syncthreads();

    g_m[blockIdx.x * 256 + tid] = 0.0f;              // exact cover: 2500*256 == N*H

    int n = blockIdx.x * 8 + (tid >> 5);
    int lane = tid & 31;

    float v0 = ldF(nf, n * 64 + lane, bf);
    float v1 = ldF(nf, n * 64 + 32 + lane, bf);
    float acc = ldF(b, lane, bf);
#pragma unroll
    for (int k = 0; k < 32; k++) {
        float a0 = __shfl_sync(0xffffffffu, v0, k);
        float a1 = __shfl_sync(0xffffffffu, v1, k);
        acc = fmaf(a0, Ws[lane * 65 + k], acc);
        acc = fmaf(a1, Ws[lane * 65 + 32 + k], acc);
    }
    g_h[n * 32 + lane] = acc;
}

// ---------------------------------------------------------------------------
// compT via tensor cores: T[n,j] = sum_k h[n,k] * W2[j,k]
// mma.m16n8k8 tf32, 3-term split (a_hi*b_hi + a_hi*b_lo + a_lo*b_hi), with
// each term in its OWN accumulator: 6 independent chains of depth 4 instead
// of R13's 2 chains of depth 12 (R13 profile: latency-bound, issue 23%).
// Partial sums combined in fp32 at the end. No reg prefetch (B is L1-resident
// after warm-up) -> fits __launch_bounds__(128,5): 5 blocks/SM, occ 31%.
// ---------------------------------------------------------------------------
__global__ void __launch_bounds__(128, 5) compTKernel() {
    __shared__ float hs[64][36];
    int tid = threadIdx.x, w = tid >> 5, l = tid & 31;
    int nb = blockIdx.x >> 1;                        // node tile (0..312)
    int jh = blockIdx.x & 1;                         // j half
    int n0 = nb * 64;

    for (int i = tid; i < 64 * 32; i += 128) {
        int r = i >> 5, c = i & 31;
        int n = n0 + r;
        hs[r][c] = (n < NN) ? g_h[n * 32 + c] : 0.0f;
    }
    __syncthreads();

    int r0 = w * 16 + (l >> 2);
    int c0 = l & 3;
    unsigned ah[16], al[16];
#pragma unroll
    for (int kk = 0; kk < 4; kk++) {
#pragma unroll
        for (int p = 0; p < 4; p++) {
            int rr = r0 + ((p & 1) ? 8 : 0);
            int cc = kk * 8 + c0 + ((p & 2) ? 4 : 0);
            float v = hs[rr][cc];
            unsigned hi = toTf32(v);
            ah[kk * 4 + p] = hi;
            al[kk * 4 + p] = toTf32(v - __uint_as_float(hi));
        }
    }

    int nr0 = n0 + w * 16 + (l >> 2);
    int nr1 = nr0 + 8;
    const float4* Bp = reinterpret_cast<const float4*>(g_B) + l;
    int jt0 = jh * JHALF;

    for (int jt = jt0; jt < jt0 + JHALF; jt += 2) {
        // tile jt: hh / hl / lh partials; tile jt+1: same
        float dhh0=0,dhh1=0,dhh2=0,dhh3=0, dhl0=0,dhl1=0,dhl2=0,dhl3=0, dlh0=0,dlh1=0,dlh2=0,dlh3=0;
        float ehh0=0,ehh1=0,ehh2=0,ehh3=0, ehl0=0,ehl1=0,ehl2=0,ehl3=0, elh0=0,elh1=0,elh2=0,elh3=0;
#pragma unroll
        for (int kk = 0; kk < 4; kk++) {
            float4 ba = Bp[(jt * 4 + kk) * 32];
            float4 bb = Bp[((jt + 1) * 4 + kk) * 32];
            unsigned a0 = ah[kk*4], a1 = ah[kk*4+1], a2 = ah[kk*4+2], a3 = ah[kk*4+3];
            unsigned l0 = al[kk*4], l1 = al[kk*4+1], l2 = al[kk*4+2], l3 = al[kk*4+3];
            unsigned b0h = __float_as_uint(ba.x), b1h = __float_as_uint(ba.y);
            unsigned b0l = __float_as_uint(ba.z), b1l = __float_as_uint(ba.w);
            unsigned c0h = __float_as_uint(bb.x), c1h = __float_as_uint(bb.y);
            unsigned c0l = __float_as_uint(bb.z), c1l = __float_as_uint(bb.w);
            MMA_TF32(dhh0,dhh1,dhh2,dhh3, a0,a1,a2,a3, b0h,b1h);
            MMA_TF32(ehh0,ehh1,ehh2,ehh3, a0,a1,a2,a3, c0h,c1h);
            MMA_TF32(dhl0,dhl1,dhl2,dhl3, a0,a1,a2,a3, b0l,b1l);
            MMA_TF32(ehl0,ehl1,ehl2,ehl3, a0,a1,a2,a3, c0l,c1l);
            MMA_TF32(dlh0,dlh1,dlh2,dlh3, l0,l1,l2,l3, b0h,b1h);
            MMA_TF32(elh0,elh1,elh2,elh3, l0,l1,l2,l3, c0h,c1h);
        }
        float d0 = dhh0 + dhl0 + dlh0, d1 = dhh1 + dhl1 + dlh1;
        float d2 = dhh2 + dhl2 + dlh2, d3 = dhh3 + dhl3 + dlh3;
        float e0 = ehh0 + ehl0 + elh0, e1 = ehh1 + ehl1 + elh1;
        float e2 = ehh2 + ehl2 + elh2, e3 = ehh3 + ehl3 + elh3;

        int jb = jt * 8 + 2 * (l & 3);
        if (nr0 < NN) {
            *reinterpret_cast<float2*>(&g_T[(size_t)nr0 * TSL + jb])     = make_float2(d0, d1);
            *reinterpret_cast<float2*>(&g_T[(size_t)nr0 * TSL + jb + 8]) = make_float2(e0, e1);
        }
        if (nr1 < NN) {
            *reinterpret_cast<float2*>(&g_T[(size_t)nr1 * TSL + jb])     = make_float2(d2, d3);
            *reinterpret_cast<float2*>(&g_T[(size_t)nr1 * TSL + jb + 8]) = make_float2(e2, e3);
        }
    }
}

// ---------------------------------------------------------------------------
// msg: 4 edges per warp, 8 lanes per edge, each lane owns a 4-channel quad.
// T loads float4 (128B/row coalesced); scatter via red.global.add.v4.f32.
// (Frozen from R11: ~25us, at its L2 gather bound.)
// ---------------------------------------------------------------------------
__global__ void msgKernel(const int* __restrict__ src, const int* __restrict__ dst,
                          const void* __restrict__ ef) {
    int bf = g_flag;
    int lane = threadIdx.x & 31;
    int g    = lane >> 3;                            // edge slot within warp (0..3)
    int sub  = lane & 7;                             // channel quad (0..7)
    int e = (blockIdx.x * (256 / 32) + (threadIdx.x >> 5)) * 4 + g;   // e < EE exact

    int s = src[e]; if ((unsigned)s >= (unsigned)NN) s = 0;
    int d = dst[e]; if ((unsigned)d >= (unsigned)NN) d = 0;

    float f0 = ldF(ef, (long)e * 16 + sub * 2,     bf);
    float f1 = ldF(ef, (long)e * 16 + sub * 2 + 1, bf);

    const float* Trow = g_T + (size_t)s * TSL;
    float4 t4[17];
#pragma unroll
    for (int dd = 0; dd < 16; dd++)
        t4[dd] = *reinterpret_cast<const float4*>(Trow + dd * 32 + sub * 4);
    t4[16] = *reinterpret_cast<const float4*>(Trow + 512 + sub * 4);   // bias quad

    float4 acc = t4[16];
#pragma unroll
    for (int dd = 0; dd < 16; dd++) {
        int sl = g * 8 + (dd >> 1);
        float c = __shfl_sync(0xffffffffu, (dd & 1) ? f1 : f0, sl);
        acc.x = fmaf(c, t4[dd].x, acc.x);
        acc.y = fmaf(c, t4[dd].y, acc.y);
        acc.z = fmaf(c, t4[dd].z, acc.z);
        acc.w = fmaf(c, t4[dd].w, acc.w);
    }

    float* outp = &g_m[d * 32 + sub * 4];            // 16B-aligned
    asm volatile("red.global.add.v4.f32 [%0], {%1, %2, %3, %4};"
                 :: "l"(outp), "f"(acc.x), "f"(acc.y), "f"(acc.z), "f"(acc.w)
                 : "memory");
}

// ---------------------------------------------------------------------------
// GRUCell (torch layout r,z,n). Warp per node; 6 independent FMA chains.
// Final step writes d_out in detected dtype. Re-zeroes g_m for replay.
// ---------------------------------------------------------------------------
__global__ void gruKernel(const void* __restrict__ W_ih, const void* __restrict__ W_hh,
                          const void* __restrict__ b_ih, const void* __restrict__ b_hh,
                          void* __restrict__ outp, int finalStep) {
    __shared__ float Wi[96 * 33];
    __shared__ float Wh[96 * 33];
    int bf = g_flag;
    int tid = threadIdx.x;
    for (int i = tid; i < 96 * 32; i += 256) {
        int j = i >> 5, k = i & 31;
        Wi[j * 33 + k] = ldF(W_ih, i, bf);
        Wh[j * 33 + k] = ldF(W_hh, i, bf);
    }
    __syncthreads();

    int n = blockIdx.x * 8 + (tid >> 5);             // grid exact: n < NN
    int lane = tid & 31;

    float mv = g_m[n * 32 + lane];
    float hv = g_h[n * 32 + lane];
    g_m[n * 32 + lane] = 0.0f;                       // reset for next step / replay

    float gi0 = ldF(b_ih, lane, bf), gi1 = ldF(b_ih, 32 + lane, bf), gi2 = ldF(b_ih, 64 + lane, bf);
    float gh0 = ldF(b_hh, lane, bf), gh1 = ldF(b_hh, 32 + lane, bf), gh2 = ldF(b_hh, 64 + lane, bf);
#pragma unroll
    for (int k = 0; k < 32; k++) {
        float mk = __shfl_sync(0xffffffffu, mv, k);
        float hk = __shfl_sync(0xffffffffu, hv, k);
        gi0 = fmaf(mk, Wi[lane * 33 + k],        gi0);
        gi1 = fmaf(mk, Wi[(32 + lane) * 33 + k], gi1);
        gi2 = fmaf(mk, Wi[(64 + lane) * 33 + k], gi2);
        gh0 = fmaf(hk, Wh[lane * 33 + k],        gh0);
        gh1 = fmaf(hk, Wh[(32 + lane) * 33 + k], gh1);
        gh2 = fmaf(hk, Wh[(64 + lane) * 33 + k], gh2);
    }
    float r  = 1.0f / (1.0f + __expf(-(gi0 + gh0)));
    float z  = 1.0f / (1.0f + __expf(-(gi1 + gh1)));
    float nn = tanhf(gi2 + r * gh2);
    float hnew = (1.0f - z) * nn + z * hv;

    if (finalStep) {
        if (bf) ((__nv_bfloat16*)outp)[n * 32 + lane] = __float2bfloat16(hnew);
        else    ((float*)outp)[n * 32 + lane] = hnew;
    } else {
        ((float*)outp)[n * 32 + lane] = hnew;        // g_h
    }
}

// ---------------------------------------------------------------------------
// Host: size-based binding (element counts) with positional fallback.
// ---------------------------------------------------------------------------
static int findBySz(const int* sizes, int n, long target, int occurrence) {
    int c = 0;
    for (int i = 0; i < n; i++)
        if ((long)sizes[i] == target) { if (c == occurrence) return i; c++; }
    return -1;
}

extern "C" void kernel_launch(void* const* d_in, const int* in_sizes, int n_in,
                              void* d_out, int out_size) {
    int i_nf = findBySz(in_sizes, n_in, (long)NN * ND, 0);
    int i_ei = findBySz(in_sizes, n_in, (long)2 * EE, 0);
    int i_ef = findBySz(in_sizes, n_in, (long)EE * ED, 0);
    int i_Wn = findBySz(in_sizes, n_in, (long)HD * ND, 0);
    int i_bn = findBySz(in_sizes, n_in, (long)HD, 0);
    int i_We = findBySz(in_sizes, n_in, (long)HD * HD * ED, 0);
    int i_be = findBySz(in_sizes, n_in, (long)HD * HD, 0);
    int i_g0 = findBySz(in_sizes, n_in, (long)3 * HD * HD, 0);
    int i_g1 = findBySz(in_sizes, n_in, (long)3 * HD * HD, 1);
    int i_q0 = findBySz(in_sizes, n_in, (long)3 * HD, 0);
    int i_q1 = findBySz(in_sizes, n_in, (long)3 * HD, 1);

    if (i_nf < 0 || i_ei < 0 || i_ef < 0 || i_Wn < 0 || i_bn < 0 ||
        i_We < 0 || i_be < 0 || i_g0 < 0 || i_g1 < 0 || i_q0 < 0 || i_q1 < 0) {
        i_nf = 0; i_ei = 1; i_ef = 2; i_Wn = 3; i_bn = 4;
        i_We = 5; i_be = 6; i_g0 = 7; i_g1 = 8; i_q0 = 9; i_q1 = 10;
    }

    const void* node_feat  = d_in[i_nf];
    const int*  edge_index = (const int*)d_in[i_ei];
    const void* edge_feat  = d_in[i_ef];
    const void* W_np       = d_in[i_Wn];
    const void* b_np       = d_in[i_bn];
    const void* W_e        = d_in[i_We];
    const void* b_e        = d_in[i_be];
    const void* W_ih       = d_in[i_g0];             // signature order: W_ih first
    const void* W_hh       = d_in[i_g1];
    const void* b_ih       = d_in[i_q0];
    const void* b_hh       = d_in[i_q1];

    const int* srcIdx = edge_index;                  // edge_index[0, :]
    const int* dstIdx = edge_index + EE;             // edge_index[1, :]

    static void* g_h_addr = nullptr;
    if (!g_h_addr) (void)cudaGetSymbolAddress(&g_h_addr, g_h);

    // Launch order: detect(0), buildB(1), nodeProj(2), compT(3 = profiled), msg(4)...
    detectKernel<<<1, 32>>>((const unsigned int*)node_feat);
    buildBKernel<<<136, 256>>>(W_e, b_e);            // 136*256 == NJT*512 exact
    nodeProjKernel<<<NN / 8, 256>>>(node_feat, W_np, b_np);

    for (int step = 0; step < 3; step++) {
        compTKernel<<<((NN + 63) / 64) * 2, 128>>>();
        msgKernel<<<EE / 32, 256>>>(srcIdx, dstIdx, edge_feat);
        int fin = (step == 2);
        void* hout = fin ? d_out : g_h_addr;
        gruKernel<<<NN / 8, 256>>>(W_ih, W_hh, b_ih, b_hh, hout, fin);
    }
}

// round 16
// speedup vs baseline: 1.8278x; 1.0175x over previous
#include <cuda_runtime.h>
#include <cuda_bf16.h>

// Problem constants (FIXED by reference): N=20000, E=160000, NODE_DIM=64, EDGE_DIM=16, H=32, STEPS=3
#define NN     20000
#define EE     160000
#define HD     32
#define ND     64
#define ED     16
#define TSL    544          // T row stride: 17 slices of 32 (16 edge-dims + bias)
#define NJT    68           // 544 / 8 n-tiles for the mma
#define JHALF  34           // jt tiles per block (j-split = 2)
#define PGRID  296          // persistent grid: 2 blocks/SM x 148 SMs
#define PWARPS (PGRID * 8)  // 2368 concurrent node-warps

// Scratch (allocation-free rule: __device__ globals)
__device__ int   g_flag;                     // 1 = float inputs are bf16, 0 = fp32 (detected)
__device__ float g_h [NN * HD];              // node hidden state (fp32 internal)
__device__ float g_m [NN * HD];              // aggregated messages
__device__ float g_T [NN * TSL];             // per-node tensor (43.5 MB, L2-resident)
__device__ float g_B [NJT * 4 * 32 * 4];     // W2 tf32 frags: [jt][kk][lane]{b0h,b1h,b0l,b1l}

namespace {
struct EagerLoad {                            // materialize device globals at process start
    EagerLoad() { void* p = nullptr; (void)cudaGetSymbolAddress(&p, g_h); }
};
EagerLoad eager_load_;
}

// Dtype-agnostic float load (branch is warp-uniform on flag).
__device__ __forceinline__ float ldF(const void* p, long i, int bf) {
    return bf ? __bfloat162float(((const __nv_bfloat16*)p)[i])
              : ((const float*)p)[i];
}

__device__ __forceinline__ unsigned toTf32(float v) {
    unsigned r; asm("cvt.rna.tf32.f32 %0, %1;" : "=r"(r) : "f"(v)); return r;
}

#define MMA_TF32(d0,d1,d2,d3,a0,a1,a2,a3,b0,b1)                         \
    asm volatile("mma.sync.aligned.m16n8k8.row.col.f32.tf32.tf32.f32 "   \
        "{%0,%1,%2,%3}, {%4,%5,%6,%7}, {%8,%9}, {%0,%1,%2,%3};"          \
        : "+f"(d0), "+f"(d1), "+f"(d2), "+f"(d3)                          \
        : "r"(a0), "r"(a1), "r"(a2), "r"(a3), "r"(b0), "r"(b1))

// ---------------------------------------------------------------------------
// Detect input dtype from node_feat bit patterns. fp32 N(0,1): bits [7,15)
// are mantissa -> uniform -> low count -> flag 0. bf16 pairs: exponent band.
// ---------------------------------------------------------------------------
__global__ void detectKernel(const unsigned int* __restrict__ nf) {
    int lane = threadIdx.x;
    int cnt = 0;
    for (int i = lane; i < 1024; i += 32) {
        unsigned int e = (nf[i] >> 7) & 0xFF;
        cnt += (e >= 110 && e <= 140) ? 1 : 0;
    }
#pragma unroll
    for (int o = 16; o > 0; o >>= 1) cnt += __shfl_down_sync(0xffffffffu, cnt, o);
    if (lane == 0) g_flag = (cnt > 512) ? 1 : 0;
}

// ---------------------------------------------------------------------------
// Build W2 tf32 B-fragments in mma frag order (hi/lo 3-term split; R14 proved
// the lo parts are load-bearing -- the weights are genuine fp32).
// Logical W2[j][k]: j = d*32+h; d<16 -> W_e[(h*32+k)*16+d]; d==16 -> b_e[h*32+k].
// Frag slot i: q=i&3 (0=b0h,1=b1h,2=b0l,3=b1l), lane=(i>>2)&31, kk=(i>>7)&3, jt=i>>9.
// ---------------------------------------------------------------------------
__global__ void buildBKernel(const void* __restrict__ We, const void* __restrict__ be) {
    int bf = g_flag;
    int i = blockIdx.x * 256 + threadIdx.x;          // grid exact: 136*256 == NJT*512
    int q    = i & 3;
    int lane = (i >> 2) & 31;
    int kk   = (i >> 7) & 3;
    int jt   = i >> 9;
    int j = jt * 8 + (lane >> 2);                    // 0..543
    int k = kk * 8 + (lane & 3) + ((q & 1) ? 4 : 0);
    int d = j >> 5, h = j & 31;
    float v = (d < 16) ? ldF(We, (h * 32 + k) * 16 + d, bf)
                       : ldF(be, h * 32 + k, bf);
    unsigned hi = toTf32(v);
    unsigned out;
    if (q >= 2) out = toTf32(v - __uint_as_float(hi));   // lo part
    else        out = hi;
    g_B[i] = __uint_as_float(out);
}

// ---------------------------------------------------------------------------
// h = node_feat @ W_np^T + b_np ; also zero g_m.
// PERSISTENT: 296 blocks stage W once, stride-loop over nodes (R15 ran 2500
// blocks -> 20 MB of redundant weight staging per launch).
// ---------------------------------------------------------------------------
__global__ void __launch_bounds__(256) nodeProjKernel(const void* __restrict__ nf,
                                                      const void* __restrict__ W,
                                                      const void* __restrict__ b) {
    __shared__ float Ws[32 * 65];
    int bf = g_flag;
    int tid = threadIdx.x;
    for (int i = tid; i < 32 * 64; i += 256)
        Ws[(i >> 6) * 65 + (i & 63)] = ldF(W, i, bf);
    __syncthreads();

    for (int zi = blockIdx.x * 256 + tid; zi < NN * HD; zi += PGRID * 256)
        g_m[zi] = 0.0f;                              // zero message buffer

    int lane = tid & 31;
    float bb = ldF(b, lane, bf);
    for (int n = blockIdx.x * 8 + (tid >> 5); n < NN; n += PWARPS) {
        float v0 = ldF(nf, (long)n * 64 + lane, bf);
        float v1 = ldF(nf, (long)n * 64 + 32 + lane, bf);
        float acc = bb;
#pragma unroll
        for (int k = 0; k < 32; k++) {
            float a0 = __shfl_sync(0xffffffffu, v0, k);
            float a1 = __shfl_sync(0xffffffffu, v1, k);
            acc = fmaf(a0, Ws[lane * 65 + k], acc);
            acc = fmaf(a1, Ws[lane * 65 + 32 + k], acc);
        }
        g_h[n * 32 + lane] = acc;
    }
}

// ---------------------------------------------------------------------------
// compT via tensor cores: T[n,j] = sum_k h[n,k] * W2[j,k]
// mma.m16n8k8 tf32, 3-term split, independent accumulator per term
// (6 chains of depth 4). Frozen from R15: 28.1us.
// ---------------------------------------------------------------------------
__global__ void __launch_bounds__(128, 5) compTKernel() {
    __shared__ float hs[64][36];
    int tid = threadIdx.x, w = tid >> 5, l = tid & 31;
    int nb = blockIdx.x >> 1;                        // node tile (0..312)
    int jh = blockIdx.x & 1;                         // j half
    int n0 = nb * 64;

    for (int i = tid; i < 64 * 32; i += 128) {
        int r = i >> 5, c = i & 31;
        int n = n0 + r;
        hs[r][c] = (n < NN) ? g_h[n * 32 + c] : 0.0f;
    }
    __syncthreads();

    int r0 = w * 16 + (l >> 2);
    int c0 = l & 3;
    unsigned ah[16], al[16];
#pragma unroll
    for (int kk = 0; kk < 4; kk++) {
#pragma unroll
        for (int p = 0; p < 4; p++) {
            int rr = r0 + ((p & 1) ? 8 : 0);
            int cc = kk * 8 + c0 + ((p & 2) ? 4 : 0);
            float v = hs[rr][cc];
            unsigned hi = toTf32(v);
            ah[kk * 4 + p] = hi;
            al[kk * 4 + p] = toTf32(v - __uint_as_float(hi));
        }
    }

    int nr0 = n0 + w * 16 + (l >> 2);
    int nr1 = nr0 + 8;
    const float4* Bp = reinterpret_cast<const float4*>(g_B) + l;
    int jt0 = jh * JHALF;

    for (int jt = jt0; jt < jt0 + JHALF; jt += 2) {
        float dhh0=0,dhh1=0,dhh2=0,dhh3=0, dhl0=0,dhl1=0,dhl2=0,dhl3=0, dlh0=0,dlh1=0,dlh2=0,dlh3=0;
        float ehh0=0,ehh1=0,ehh2=0,ehh3=0, ehl0=0,ehl1=0,ehl2=0,ehl3=0, elh0=0,elh1=0,elh2=0,elh3=0;
#pragma unroll
        for (int kk = 0; kk < 4; kk++) {
            float4 ba = Bp[(jt * 4 + kk) * 32];
            float4 bb = Bp[((jt + 1) * 4 + kk) * 32];
            unsigned a0 = ah[kk*4], a1 = ah[kk*4+1], a2 = ah[kk*4+2], a3 = ah[kk*4+3];
            unsigned l0 = al[kk*4], l1 = al[kk*4+1], l2 = al[kk*4+2], l3 = al[kk*4+3];
            unsigned b0h = __float_as_uint(ba.x), b1h = __float_as_uint(ba.y);
            unsigned b0l = __float_as_uint(ba.z), b1l = __float_as_uint(ba.w);
            unsigned c0h = __float_as_uint(bb.x), c1h = __float_as_uint(bb.y);
            unsigned c0l = __float_as_uint(bb.z), c1l = __float_as_uint(bb.w);
            MMA_TF32(dhh0,dhh1,dhh2,dhh3, a0,a1,a2,a3, b0h,b1h);
            MMA_TF32(ehh0,ehh1,ehh2,ehh3, a0,a1,a2,a3, c0h,c1h);
            MMA_TF32(dhl0,dhl1,dhl2,dhl3, a0,a1,a2,a3, b0l,b1l);
            MMA_TF32(ehl0,ehl1,ehl2,ehl3, a0,a1,a2,a3, c0l,c1l);
            MMA_TF32(dlh0,dlh1,dlh2,dlh3, l0,l1,l2,l3, b0h,b1h);
            MMA_TF32(elh0,elh1,elh2,elh3, l0,l1,l2,l3, c0h,c1h);
        }
        float d0 = dhh0 + dhl0 + dlh0, d1 = dhh1 + dhl1 + dlh1;
        float d2 = dhh2 + dhl2 + dlh2, d3 = dhh3 + dhl3 + dlh3;
        float e0 = ehh0 + ehl0 + elh0, e1 = ehh1 + ehl1 + elh1;
        float e2 = ehh2 + ehl2 + elh2, e3 = ehh3 + ehl3 + elh3;

        int jb = jt * 8 + 2 * (l & 3);
        if (nr0 < NN) {
            *reinterpret_cast<float2*>(&g_T[(size_t)nr0 * TSL + jb])     = make_float2(d0, d1);
            *reinterpret_cast<float2*>(&g_T[(size_t)nr0 * TSL + jb + 8]) = make_float2(e0, e1);
        }
        if (nr1 < NN) {
            *reinterpret_cast<float2*>(&g_T[(size_t)nr1 * TSL + jb])     = make_float2(d2, d3);
            *reinterpret_cast<float2*>(&g_T[(size_t)nr1 * TSL + jb + 8]) = make_float2(e2, e3);
        }
    }
}

// ---------------------------------------------------------------------------
// msg: 4 edges per warp, 8 lanes per edge, each lane owns a 4-channel quad.
// T loads float4 (128B/row coalesced); scatter via red.global.add.v4.f32.
// (Frozen from R11: ~25us, at its L2 gather bound.)
// ---------------------------------------------------------------------------
__global__ void msgKernel(const int* __restrict__ src, const int* __restrict__ dst,
                          const void* __restrict__ ef) {
    int bf = g_flag;
    int lane = threadIdx.x & 31;
    int g    = lane >> 3;                            // edge slot within warp (0..3)
    int sub  = lane & 7;                             // channel quad (0..7)
    int e = (blockIdx.x * (256 / 32) + (threadIdx.x >> 5)) * 4 + g;   // e < EE exact

    int s = src[e]; if ((unsigned)s >= (unsigned)NN) s = 0;
    int d = dst[e]; if ((unsigned)d >= (unsigned)NN) d = 0;

    float f0 = ldF(ef, (long)e * 16 + sub * 2,     bf);
    float f1 = ldF(ef, (long)e * 16 + sub * 2 + 1, bf);

    const float* Trow = g_T + (size_t)s * TSL;
    float4 t4[17];
#pragma unroll
    for (int dd = 0; dd < 16; dd++)
        t4[dd] = *reinterpret_cast<const float4*>(Trow + dd * 32 + sub * 4);
    t4[16] = *reinterpret_cast<const float4*>(Trow + 512 + sub * 4);   // bias quad

    float4 acc = t4[16];
#pragma unroll
    for (int dd = 0; dd < 16; dd++) {
        int sl = g * 8 + (dd >> 1);
        float c = __shfl_sync(0xffffffffu, (dd & 1) ? f1 : f0, sl);
        acc.x = fmaf(c, t4[dd].x, acc.x);
        acc.y = fmaf(c, t4[dd].y, acc.y);
        acc.z = fmaf(c, t4[dd].z, acc.z);
        acc.w = fmaf(c, t4[dd].w, acc.w);
    }

    float* outp = &g_m[d * 32 + sub * 4];            // 16B-aligned
    asm volatile("red.global.add.v4.f32 [%0], {%1, %2, %3, %4};"
                 :: "l"(outp), "f"(acc.x), "f"(acc.y), "f"(acc.z), "f"(acc.w)
                 : "memory");
}

// ---------------------------------------------------------------------------
// GRUCell (torch layout r,z,n). PERSISTENT: 296 blocks stage Wi/Wh ONCE
// (R15 ran 2500 blocks -> 60 MB of redundant weight staging per launch),
// then stride-loop over nodes. Re-zeroes g_m for replay.
// ---------------------------------------------------------------------------
__global__ void __launch_bounds__(256) gruKernel(const void* __restrict__ W_ih,
                                                 const void* __restrict__ W_hh,
                                                 const void* __restrict__ b_ih,
                                                 const void* __restrict__ b_hh,
                                                 void* __restrict__ outp, int finalStep) {
    __shared__ float Wi[96 * 33];
    __shared__ float Wh[96 * 33];
    int bf = g_flag;
    int tid = threadIdx.x;
    for (int i = tid; i < 96 * 32; i += 256) {
        int j = i >> 5, k = i & 31;
        Wi[j * 33 + k] = ldF(W_ih, i, bf);
        Wh[j * 33 + k] = ldF(W_hh, i, bf);
    }
    __syncthreads();

    int lane = tid & 31;
    float bi0 = ldF(b_ih, lane, bf), bi1 = ldF(b_ih, 32 + lane, bf), bi2 = ldF(b_ih, 64 + lane, bf);
    float bh0 = ldF(b_hh, lane, bf), bh1 = ldF(b_hh, 32 + lane, bf), bh2 = ldF(b_hh, 64 + lane, bf);

    for (int n = blockIdx.x * 8 + (tid >> 5); n < NN; n += PWARPS) {
        float mv = g_m[n * 32 + lane];
        float hv = g_h[n * 32 + lane];
        g_m[n * 32 + lane] = 0.0f;                   // reset for next step / replay

        float gi0 = bi0, gi1 = bi1, gi2 = bi2;
        float gh0 = bh0, gh1 = bh1, gh2 = bh2;
#pragma unroll
        for (int k = 0; k < 32; k++) {
            float mk = __shfl_sync(0xffffffffu, mv, k);
            float hk = __shfl_sync(0xffffffffu, hv, k);
            gi0 = fmaf(mk, Wi[lane * 33 + k],        gi0);
            gi1 = fmaf(mk, Wi[(32 + lane) * 33 + k], gi1);
            gi2 = fmaf(mk, Wi[(64 + lane) * 33 + k], gi2);
            gh0 = fmaf(hk, Wh[lane * 33 + k],        gh0);
            gh1 = fmaf(hk, Wh[(32 + lane) * 33 + k], gh1);
            gh2 = fmaf(hk, Wh[(64 + lane) * 33 + k], gh2);
        }
        float r  = 1.0f / (1.0f + __expf(-(gi0 + gh0)));
        float z  = 1.0f / (1.0f + __expf(-(gi1 + gh1)));
        float nn = tanhf(gi2 + r * gh2);
        float hnew = (1.0f - z) * nn + z * hv;

        if (finalStep) {
            if (bf) ((__nv_bfloat16*)outp)[n * 32 + lane] = __float2bfloat16(hnew);
            else    ((float*)outp)[n * 32 + lane] = hnew;
        } else {
            ((float*)outp)[n * 32 + lane] = hnew;    // g_h
        }
    }
}

// ---------------------------------------------------------------------------
// Host: size-based binding (element counts) with positional fallback.
// ---------------------------------------------------------------------------
static int findBySz(const int* sizes, int n, long target, int occurrence) {
    int c = 0;
    for (int i = 0; i < n; i++)
        if ((long)sizes[i] == target) { if (c == occurrence) return i; c++; }
    return -1;
}

extern "C" void kernel_launch(void* const* d_in, const int* in_sizes, int n_in,
                              void* d_out, int out_size) {
    int i_nf = findBySz(in_sizes, n_in, (long)NN * ND, 0);
    int i_ei = findBySz(in_sizes, n_in, (long)2 * EE, 0);
    int i_ef = findBySz(in_sizes, n_in, (long)EE * ED, 0);
    int i_Wn = findBySz(in_sizes, n_in, (long)HD * ND, 0);
    int i_bn = findBySz(in_sizes, n_in, (long)HD, 0);
    int i_We = findBySz(in_sizes, n_in, (long)HD * HD * ED, 0);
    int i_be = findBySz(in_sizes, n_in, (long)HD * HD, 0);
    int i_g0 = findBySz(in_sizes, n_in, (long)3 * HD * HD, 0);
    int i_g1 = findBySz(in_sizes, n_in, (long)3 * HD * HD, 1);
    int i_q0 = findBySz(in_sizes, n_in, (long)3 * HD, 0);
    int i_q1 = findBySz(in_sizes, n_in, (long)3 * HD, 1);

    if (i_nf < 0 || i_ei < 0 || i_ef < 0 || i_Wn < 0 || i_bn < 0 ||
        i_We < 0 || i_be < 0 || i_g0 < 0 || i_g1 < 0 || i_q0 < 0 || i_q1 < 0) {
        i_nf = 0; i_ei = 1; i_ef = 2; i_Wn = 3; i_bn = 4;
        i_We = 5; i_be = 6; i_g0 = 7; i_g1 = 8; i_q0 = 9; i_q1 = 10;
    }

    const void* node_feat  = d_in[i_nf];
    const int*  edge_index = (const int*)d_in[i_ei];
    const void* edge_feat  = d_in[i_ef];
    const void* W_np       = d_in[i_Wn];
    const void* b_np       = d_in[i_bn];
    const void* W_e        = d_in[i_We];
    const void* b_e        = d_in[i_be];
    const void* W_ih       = d_in[i_g0];             // signature order: W_ih first
    const void* W_hh       = d_in[i_g1];
    const void* b_ih       = d_in[i_q0];
    const void* b_hh       = d_in[i_q1];

    const int* srcIdx = edge_index;                  // edge_index[0, :]
    const int* dstIdx = edge_index + EE;             // edge_index[1, :]

    static void* g_h_addr = nullptr;
    if (!g_h_addr) (void)cudaGetSymbolAddress(&g_h_addr, g_h);

    // Launch order: detect(0), buildB(1), nodeProj(2), compT(3 = profiled), msg(4)...
    detectKernel<<<1, 32>>>((const unsigned int*)node_feat);
    buildBKernel<<<136, 256>>>(W_e, b_e);            // 136*256 == NJT*512 exact
    nodeProjKernel<<<PGRID, 256>>>(node_feat, W_np, b_np);

    for (int step = 0; step < 3; step++) {
        compTKernel<<<((NN + 63) / 64) * 2, 128>>>();
        msgKernel<<<EE / 32, 256>>>(srcIdx, dstIdx, edge_feat);
        int fin = (step == 2);
        void* hout = fin ? d_out : g_h_addr;
        gruKernel<<<PGRID, 256>>>(W_ih, W_hh, b_ih, b_hh, hout, fin);
    }
}

// round 17
// speedup vs baseline: 1.9614x; 1.0731x over previous
#include <cuda_runtime.h>
#include <cuda_bf16.h>

// Problem constants (FIXED by reference): N=20000, E=160000, NODE_DIM=64, EDGE_DIM=16, H=32, STEPS=3
#define NN     20000
#define EE     160000
#define HD     32
#define ND     64
#define ED     16
#define TSL    544          // T row stride: 17 slices of 32 (16 edge-dims + bias)
#define NJT    68           // 544 / 8 n-tiles for the mma
#define JHALF  34           // jt tiles per block (j-split = 2)
#define PGRID  296          // persistent grid: 2 blocks/SM x 148 SMs
#define PWARPS (PGRID * 8)  // 2368 concurrent warps

// Scratch (allocation-free rule: __device__ globals)
__device__ int   g_flag;                     // 1 = float inputs are bf16, 0 = fp32 (detected)
__device__ float g_h [NN * HD];              // node hidden state (fp32 internal)
__device__ float g_m [NN * HD];              // aggregated messages
__device__ float g_T [NN * TSL];             // per-node tensor (43.5 MB, L2-resident)
__device__ float g_B [NJT * 4 * 32 * 4];     // W2 tf32 frags: [jt][kk][lane]{b0h,b1h,b0l,b1l}

namespace {
struct EagerLoad {                            // materialize device globals at process start
    EagerLoad() { void* p = nullptr; (void)cudaGetSymbolAddress(&p, g_h); }
};
EagerLoad eager_load_;
}

// Dtype-agnostic float load (branch is warp-uniform on flag).
__device__ __forceinline__ float ldF(const void* p, long i, int bf) {
    return bf ? __bfloat162float(((const __nv_bfloat16*)p)[i])
              : ((const float*)p)[i];
}

__device__ __forceinline__ unsigned toTf32(float v) {
    unsigned r; asm("cvt.rna.tf32.f32 %0, %1;" : "=r"(r) : "f"(v)); return r;
}

#define MMA_TF32(d0,d1,d2,d3,a0,a1,a2,a3,b0,b1)                         \
    asm volatile("mma.sync.aligned.m16n8k8.row.col.f32.tf32.tf32.f32 "   \
        "{%0,%1,%2,%3}, {%4,%5,%6,%7}, {%8,%9}, {%0,%1,%2,%3};"          \
        : "+f"(d0), "+f"(d1), "+f"(d2), "+f"(d3)                          \
        : "r"(a0), "r"(a1), "r"(a2), "r"(a3), "r"(b0), "r"(b1))

// ---------------------------------------------------------------------------
// buildB + per-block dtype self-detection (merged; R11-proven pattern).
// Block 0 publishes g_flag for the downstream kernels.
// Builds W2 tf32 B-fragments in mma frag order (hi/lo 3-term split; R14
// proved the lo parts are load-bearing -- the weights are genuine fp32).
// Logical W2[j][k]: j = d*32+h; d<16 -> W_e[(h*32+k)*16+d]; d==16 -> b_e[h*32+k].
// Frag slot i: q=i&3 (0=b0h,1=b1h,2=b0l,3=b1l), lane=(i>>2)&31, kk=(i>>7)&3, jt=i>>9.
// ---------------------------------------------------------------------------
__global__ void buildBKernel(const unsigned int* __restrict__ nf,
                             const void* __restrict__ We, const void* __restrict__ be) {
    __shared__ int sflag;
    int tid = threadIdx.x;
    if (tid < 32) {
        int cnt = 0;
        for (int i = tid; i < 1024; i += 32) {
            unsigned int e = (nf[i] >> 7) & 0xFF;
            cnt += (e >= 110 && e <= 140) ? 1 : 0;
        }
#pragma unroll
        for (int o = 16; o > 0; o >>= 1) cnt += __shfl_down_sync(0xffffffffu, cnt, o);
        if (tid == 0) {
            sflag = (cnt > 512) ? 1 : 0;
            if (blockIdx.x == 0) g_flag = sflag;
        }
    }
    __syncthreads();
    int bf = sflag;

    int i = blockIdx.x * 256 + tid;                  // grid exact: 136*256 == NJT*512
    int q    = i & 3;
    int lane = (i >> 2) & 31;
    int kk   = (i >> 7) & 3;
    int jt   = i >> 9;
    int j = jt * 8 + (lane >> 2);                    // 0..543
    int k = kk * 8 + (lane & 3) + ((q & 1) ? 4 : 0);
    int d = j >> 5, h = j & 31;
    float v = (d < 16) ? ldF(We, (h * 32 + k) * 16 + d, bf)
                       : ldF(be, h * 32 + k, bf);
    unsigned hi = toTf32(v);
    unsigned out;
    if (q >= 2) out = toTf32(v - __uint_as_float(hi));   // lo part
    else        out = hi;
    g_B[i] = __uint_as_float(out);
}

// ---------------------------------------------------------------------------
// h = node_feat @ W_np^T + b_np ; also zero g_m.
// PERSISTENT: 296 blocks stage W once, stride-loop over nodes.
// ---------------------------------------------------------------------------
__global__ void __launch_bounds__(256) nodeProjKernel(const void* __restrict__ nf,
                                                      const void* __restrict__ W,
                                                      const void* __restrict__ b) {
    __shared__ float Ws[32 * 65];
    int bf = g_flag;
    int tid = threadIdx.x;
    for (int i = tid; i < 32 * 64; i += 256)
        Ws[(i >> 6) * 65 + (i & 63)] = ldF(W, i, bf);
    __syncthreads();

    for (int zi = blockIdx.x * 256 + tid; zi < NN * HD; zi += PGRID * 256)
        g_m[zi] = 0.0f;                              // zero message buffer

    int lane = tid & 31;
    float bb = ldF(b, lane, bf);
    for (int n = blockIdx.x * 8 + (tid >> 5); n < NN; n += PWARPS) {
        float v0 = ldF(nf, (long)n * 64 + lane, bf);
        float v1 = ldF(nf, (long)n * 64 + 32 + lane, bf);
        float acc = bb;
#pragma unroll
        for (int k = 0; k < 32; k++) {
            float a0 = __shfl_sync(0xffffffffu, v0, k);
            float a1 = __shfl_sync(0xffffffffu, v1, k);
            acc = fmaf(a0, Ws[lane * 65 + k], acc);
            acc = fmaf(a1, Ws[lane * 65 + 32 + k], acc);
        }
        g_h[n * 32 + lane] = acc;
    }
}

// ---------------------------------------------------------------------------
// compT via tensor cores: T[n,j] = sum_k h[n,k] * W2[j,k]
// mma.m16n8k8 tf32, 3-term split, independent accumulator per term
// (6 chains of depth 4). Frozen from R15: 28.1us.
// ---------------------------------------------------------------------------
__global__ void __launch_bounds__(128, 5) compTKernel() {
    __shared__ float hs[64][36];
    int tid = threadIdx.x, w = tid >> 5, l = tid & 31;
    int nb = blockIdx.x >> 1;                        // node tile (0..312)
    int jh = blockIdx.x & 1;                         // j half
    int n0 = nb * 64;

    for (int i = tid; i < 64 * 32; i += 128) {
        int r = i >> 5, c = i & 31;
        int n = n0 + r;
        hs[r][c] = (n < NN) ? g_h[n * 32 + c] : 0.0f;
    }
    __syncthreads();

    int r0 = w * 16 + (l >> 2);
    int c0 = l & 3;
    unsigned ah[16], al[16];
#pragma unroll
    for (int kk = 0; kk < 4; kk++) {
#pragma unroll
        for (int p = 0; p < 4; p++) {
            int rr = r0 + ((p & 1) ? 8 : 0);
            int cc = kk * 8 + c0 + ((p & 2) ? 4 : 0);
            float v = hs[rr][cc];
            unsigned hi = toTf32(v);
            ah[kk * 4 + p] = hi;
            al[kk * 4 + p] = toTf32(v - __uint_as_float(hi));
        }
    }

    int nr0 = n0 + w * 16 + (l >> 2);
    int nr1 = nr0 + 8;
    const float4* Bp = reinterpret_cast<const float4*>(g_B) + l;
    int jt0 = jh * JHALF;

    for (int jt = jt0; jt < jt0 + JHALF; jt += 2) {
        float dhh0=0,dhh1=0,dhh2=0,dhh3=0, dhl0=0,dhl1=0,dhl2=0,dhl3=0, dlh0=0,dlh1=0,dlh2=0,dlh3=0;
        float ehh0=0,ehh1=0,ehh2=0,ehh3=0, ehl0=0,ehl1=0,ehl2=0,ehl3=0, elh0=0,elh1=0,elh2=0,elh3=0;
#pragma unroll
        for (int kk = 0; kk < 4; kk++) {
            float4 ba = Bp[(jt * 4 + kk) * 32];
            float4 bb = Bp[((jt + 1) * 4 + kk) * 32];
            unsigned a0 = ah[kk*4], a1 = ah[kk*4+1], a2 = ah[kk*4+2], a3 = ah[kk*4+3];
            unsigned l0 = al[kk*4], l1 = al[kk*4+1], l2 = al[kk*4+2], l3 = al[kk*4+3];
            unsigned b0h = __float_as_uint(ba.x), b1h = __float_as_uint(ba.y);
            unsigned b0l = __float_as_uint(ba.z), b1l = __float_as_uint(ba.w);
            unsigned c0h = __float_as_uint(bb.x), c1h = __float_as_uint(bb.y);
            unsigned c0l = __float_as_uint(bb.z), c1l = __float_as_uint(bb.w);
            MMA_TF32(dhh0,dhh1,dhh2,dhh3, a0,a1,a2,a3, b0h,b1h);
            MMA_TF32(ehh0,ehh1,ehh2,ehh3, a0,a1,a2,a3, c0h,c1h);
            MMA_TF32(dhl0,dhl1,dhl2,dhl3, a0,a1,a2,a3, b0l,b1l);
            MMA_TF32(ehl0,ehl1,ehl2,ehl3, a0,a1,a2,a3, c0l,c1l);
            MMA_TF32(dlh0,dlh1,dlh2,dlh3, l0,l1,l2,l3, b0h,b1h);
            MMA_TF32(elh0,elh1,elh2,elh3, l0,l1,l2,l3, c0h,c1h);
        }
        float d0 = dhh0 + dhl0 + dlh0, d1 = dhh1 + dhl1 + dlh1;
        float d2 = dhh2 + dhl2 + dlh2, d3 = dhh3 + dhl3 + dlh3;
        float e0 = ehh0 + ehl0 + elh0, e1 = ehh1 + ehl1 + elh1;
        float e2 = ehh2 + ehl2 + elh2, e3 = ehh3 + ehl3 + elh3;

        int jb = jt * 8 + 2 * (l & 3);
        if (nr0 < NN) {
            *reinterpret_cast<float2*>(&g_T[(size_t)nr0 * TSL + jb])     = make_float2(d0, d1);
            *reinterpret_cast<float2*>(&g_T[(size_t)nr0 * TSL + jb + 8]) = make_float2(e0, e1);
        }
        if (nr1 < NN) {
            *reinterpret_cast<float2*>(&g_T[(size_t)nr1 * TSL + jb])     = make_float2(d2, d3);
            *reinterpret_cast<float2*>(&g_T[(size_t)nr1 * TSL + jb + 8]) = make_float2(e2, e3);
        }
    }
}

// ---------------------------------------------------------------------------
// msg: 4 edges per warp, 8 lanes per edge, each lane owns a 4-channel quad.
// T loads float4 (128B/row coalesced); scatter via red.global.add.v4.f32.
// (Frozen from R11: ~24us, at its L2 gather bound. Now at profiled index 3.)
// ---------------------------------------------------------------------------
__global__ void msgKernel(const int* __restrict__ src, const int* __restrict__ dst,
                          const void* __restrict__ ef) {
    int bf = g_flag;
    int lane = threadIdx.x & 31;
    int g    = lane >> 3;                            // edge slot within warp (0..3)
    int sub  = lane & 7;                             // channel quad (0..7)
    int e = (blockIdx.x * (256 / 32) + (threadIdx.x >> 5)) * 4 + g;   // e < EE exact

    int s = src[e]; if ((unsigned)s >= (unsigned)NN) s = 0;
    int d = dst[e]; if ((unsigned)d >= (unsigned)NN) d = 0;

    float f0 = ldF(ef, (long)e * 16 + sub * 2,     bf);
    float f1 = ldF(ef, (long)e * 16 + sub * 2 + 1, bf);

    const float* Trow = g_T + (size_t)s * TSL;
    float4 t4[17];
#pragma unroll
    for (int dd = 0; dd < 16; dd++)
        t4[dd] = *reinterpret_cast<const float4*>(Trow + dd * 32 + sub * 4);
    t4[16] = *reinterpret_cast<const float4*>(Trow + 512 + sub * 4);   // bias quad

    float4 acc = t4[16];
#pragma unroll
    for (int dd = 0; dd < 16; dd++) {
        int sl = g * 8 + (dd >> 1);
        float c = __shfl_sync(0xffffffffu, (dd & 1) ? f1 : f0, sl);
        acc.x = fmaf(c, t4[dd].x, acc.x);
        acc.y = fmaf(c, t4[dd].y, acc.y);
        acc.z = fmaf(c, t4[dd].z, acc.z);
        acc.w = fmaf(c, t4[dd].w, acc.w);
    }

    float* outp = &g_m[d * 32 + sub * 4];            // 16B-aligned
    asm volatile("red.global.add.v4.f32 [%0], {%1, %2, %3, %4};"
                 :: "l"(outp), "f"(acc.x), "f"(acc.y), "f"(acc.z), "f"(acc.w)
                 : "memory");
}

// ---------------------------------------------------------------------------
// GRUCell (torch layout r,z,n). PERSISTENT + 8-node ILP: for each k the 6
// weights are loaded ONCE and applied to 8 register-resident nodes -> 8x
// fewer LDS than R16 (gru was LSU-issue-bound: 192 LDS/node).
// Warp processes an 8-node batch; 2500 batches over 2368 warps.
// ---------------------------------------------------------------------------
__global__ void __launch_bounds__(256) gruKernel(const void* __restrict__ W_ih,
                                                 const void* __restrict__ W_hh,
                                                 const void* __restrict__ b_ih,
                                                 const void* __restrict__ b_hh,
                                                 void* __restrict__ outp, int finalStep) {
    __shared__ float Wi[96 * 33];
    __shared__ float Wh[96 * 33];
    int bf = g_flag;
    int tid = threadIdx.x;
    for (int i = tid; i < 96 * 32; i += 256) {
        int j = i >> 5, k = i & 31;
        Wi[j * 33 + k] = ldF(W_ih, i, bf);
        Wh[j * 33 + k] = ldF(W_hh, i, bf);
    }
    __syncthreads();

    int lane = tid & 31;
    float bi0 = ldF(b_ih, lane, bf), bi1 = ldF(b_ih, 32 + lane, bf), bi2 = ldF(b_ih, 64 + lane, bf);
    float bh0 = ldF(b_hh, lane, bf), bh1 = ldF(b_hh, 32 + lane, bf), bh2 = ldF(b_hh, 64 + lane, bf);

    int warpId = blockIdx.x * 8 + (tid >> 5);
    for (int batch = warpId; batch < NN / 8; batch += PWARPS) {   // 2500 batches
        int n0 = batch * 8;
        float mv[8], hv[8];
#pragma unroll
        for (int i = 0; i < 8; i++) {
            mv[i] = g_m[(n0 + i) * 32 + lane];
            hv[i] = g_h[(n0 + i) * 32 + lane];
            g_m[(n0 + i) * 32 + lane] = 0.0f;        // reset for next step / replay
        }

        float gi0[8], gi1[8], gi2[8], gh0[8], gh1[8], gh2[8];
#pragma unroll
        for (int i = 0; i < 8; i++) {
            gi0[i] = bi0; gi1[i] = bi1; gi2[i] = bi2;
            gh0[i] = bh0; gh1[i] = bh1; gh2[i] = bh2;
        }

#pragma unroll
        for (int k = 0; k < 32; k++) {
            float wi0 = Wi[lane * 33 + k];
            float wi1 = Wi[(32 + lane) * 33 + k];
            float wi2 = Wi[(64 + lane) * 33 + k];
            float wh0 = Wh[lane * 33 + k];
            float wh1 = Wh[(32 + lane) * 33 + k];
            float wh2 = Wh[(64 + lane) * 33 + k];
#pragma unroll
            for (int i = 0; i < 8; i++) {
                float mk = __shfl_sync(0xffffffffu, mv[i], k);
                float hk = __shfl_sync(0xffffffffu, hv[i], k);
                gi0[i] = fmaf(mk, wi0, gi0[i]);
                gi1[i] = fmaf(mk, wi1, gi1[i]);
                gi2[i] = fmaf(mk, wi2, gi2[i]);
                gh0[i] = fmaf(hk, wh0, gh0[i]);
                gh1[i] = fmaf(hk, wh1, gh1[i]);
                gh2[i] = fmaf(hk, wh2, gh2[i]);
            }
        }

#pragma unroll
        for (int i = 0; i < 8; i++) {
            float r  = 1.0f / (1.0f + __expf(-(gi0[i] + gh0[i])));
            float z  = 1.0f / (1.0f + __expf(-(gi1[i] + gh1[i])));
            float nn = tanhf(gi2[i] + r * gh2[i]);
            float hnew = (1.0f - z) * nn + z * hv[i];
            int n = n0 + i;
            if (finalStep) {
                if (bf) ((__nv_bfloat16*)outp)[n * 32 + lane] = __float2bfloat16(hnew);
                else    ((float*)outp)[n * 32 + lane] = hnew;
            } else {
                ((float*)outp)[n * 32 + lane] = hnew;    // g_h
            }
        }
    }
}

// ---------------------------------------------------------------------------
// Host: size-based binding (element counts) with positional fallback.
// ---------------------------------------------------------------------------
static int findBySz(const int* sizes, int n, long target, int occurrence) {
    int c = 0;
    for (int i = 0; i < n; i++)
        if ((long)sizes[i] == target) { if (c == occurrence) return i; c++; }
    return -1;
}

extern "C" void kernel_launch(void* const* d_in, const int* in_sizes, int n_in,
                              void* d_out, int out_size) {
    int i_nf = findBySz(in_sizes, n_in, (long)NN * ND, 0);
    int i_ei = findBySz(in_sizes, n_in, (long)2 * EE, 0);
    int i_ef = findBySz(in_sizes, n_in, (long)EE * ED, 0);
    int i_Wn = findBySz(in_sizes, n_in, (long)HD * ND, 0);
    int i_bn = findBySz(in_sizes, n_in, (long)HD, 0);
    int i_We = findBySz(in_sizes, n_in, (long)HD * HD * ED, 0);
    int i_be = findBySz(in_sizes, n_in, (long)HD * HD, 0);
    int i_g0 = findBySz(in_sizes, n_in, (long)3 * HD * HD, 0);
    int i_g1 = findBySz(in_sizes, n_in, (long)3 * HD * HD, 1);
    int i_q0 = findBySz(in_sizes, n_in, (long)3 * HD, 0);
    int i_q1 = findBySz(in_sizes, n_in, (long)3 * HD, 1);

    if (i_nf < 0 || i_ei < 0 || i_ef < 0 || i_Wn < 0 || i_bn < 0 ||
        i_We < 0 || i_be < 0 || i_g0 < 0 || i_g1 < 0 || i_q0 < 0 || i_q1 < 0) {
        i_nf = 0; i_ei = 1; i_ef = 2; i_Wn = 3; i_bn = 4;
        i_We = 5; i_be = 6; i_g0 = 7; i_g1 = 8; i_q0 = 9; i_q1 = 10;
    }

    const void* node_feat  = d_in[i_nf];
    const int*  edge_index = (const int*)d_in[i_ei];
    const void* edge_feat  = d_in[i_ef];
    const void* W_np       = d_in[i_Wn];
    const void* b_np       = d_in[i_bn];
    const void* W_e        = d_in[i_We];
    const void* b_e        = d_in[i_be];
    const void* W_ih       = d_in[i_g0];             // signature order: W_ih first
    const void* W_hh       = d_in[i_g1];
    const void* b_ih       = d_in[i_q0];
    const void* b_hh       = d_in[i_q1];

    const int* srcIdx = edge_index;                  // edge_index[0, :]
    const int* dstIdx = edge_index + EE;             // edge_index[1, :]

    static void* g_h_addr = nullptr;
    if (!g_h_addr) (void)cudaGetSymbolAddress(&g_h_addr, g_h);

    // Launch order: buildB(0), nodeProj(1), compT(2), msg(3 = profiled), gru(4)...
    buildBKernel<<<136, 256>>>((const unsigned int*)node_feat, W_e, b_e);
    nodeProjKernel<<<PGRID, 256>>>(node_feat, W_np, b_np);

    for (int step = 0; step < 3; step++) {
        compTKernel<<<((NN + 63) / 64) * 2, 128>>>();
        msgKernel<<<EE / 32, 256>>>(srcIdx, dstIdx, edge_feat);
        int fin = (step == 2);
        void* hout = fin ? d_out : g_h_addr;
        gruKernel<<<PGRID, 256>>>(W_ih, W_hh, b_ih, b_hh, hout, fin);
    }
}